// round 7
// baseline (speedup 1.0000x reference)
#include <cuda_runtime.h>
#include <cuda_bf16.h>
#include <math.h>
#include <stdint.h>

#define NA 100
#define DM 256
#define HID 256
#define BATCH 64
#define NPAIR 4950
#define LDA 101
#define PT 64           // pairs per CTA tile
#define PTILES 78       // ceil(4950/64)
#define MAX_SWEEPS 16
#define ROT_ROUNDS (MAX_SWEEPS * 99)

// ---------------- device scratch (no allocation allowed) ----------------
__device__ float g_R[BATCH * NA * NA];
__device__ float g_vols[BATCH * NA];
__device__ __nv_bfloat16 g_w1t_hi[HID * DM];  // [n][k] K-major
__device__ __nv_bfloat16 g_w1t_lo[HID * DM];
__device__ float2 g_rot[(size_t)BATCH * ROT_ROUNDS * 64];  // rotation log
__device__ float g_evals[BATCH * 128];
__device__ int g_flag[BATCH];
__device__ int g_done[BATCH];

__device__ __forceinline__ uint32_t smem_u32(const void* p) {
  uint32_t a;
  asm("{ .reg .u64 t; cvta.to.shared.u64 t, %1; cvt.u32.u64 %0, t; }"
      : "=r"(a) : "l"(p));
  return a;
}
__device__ __forceinline__ void ldsm_x4(uint32_t (&r)[4], uint32_t addr) {
  asm volatile(
      "ldmatrix.sync.aligned.m8n8.x4.shared.b16 {%0,%1,%2,%3}, [%4];"
      : "=r"(r[0]), "=r"(r[1]), "=r"(r[2]), "=r"(r[3]) : "r"(addr));
}
__device__ __forceinline__ void ldsm_x2(uint32_t (&r)[2], uint32_t addr) {
  asm volatile(
      "ldmatrix.sync.aligned.m8n8.x2.shared.b16 {%0,%1}, [%2];"
      : "=r"(r[0]), "=r"(r[1]) : "r"(addr));
}
__device__ __forceinline__ void mma16816(float (&d)[4], const uint32_t (&a)[4],
                                         const uint32_t (&b)[2]) {
  asm volatile(
      "mma.sync.aligned.m16n8k16.row.col.f32.bf16.bf16.f32 "
      "{%0,%1,%2,%3}, {%4,%5,%6,%7}, {%8,%9}, {%0,%1,%2,%3};"
      : "+f"(d[0]), "+f"(d[1]), "+f"(d[2]), "+f"(d[3])
      : "r"(a[0]), "r"(a[1]), "r"(a[2]), "r"(a[3]), "r"(b[0]), "r"(b[1]));
}
__device__ __forceinline__ void pq_from(int round, int k, int* pp, int* qq) {
  const int m = NA - 1;
  int p, q;
  if (k == 0) { p = m; q = round % m; }
  else { p = (round + k) % m; q = (round - k + m) % m; }
  if (p > q) { int t = p; p = q; q = t; }
  *pp = p; *qq = q;
}

// ---------------------------------------------------------------------------
__global__ void zero_flags() {
  int t = threadIdx.x;
  if (t < BATCH) { g_flag[t] = 0; g_done[t] = 0; }
}

// ---------------------------------------------------------------------------
__global__ void prep_w1t(const float* __restrict__ w1) {
  int n = blockIdx.x, k = threadIdx.x;
  float v = w1[k * HID + n];
  __nv_bfloat16 h = __float2bfloat16(v);
  float r = v - __bfloat162float(h);
  g_w1t_hi[n * DM + k] = h;
  g_w1t_lo[n * DM + k] = __float2bfloat16(r);
}

// ---------------------------------------------------------------------------
__global__ __launch_bounds__(256) void vols_kernel(
    const float* __restrict__ x, const float* __restrict__ w1,
    const float* __restrict__ b1, const float* __restrict__ w2,
    const float* __restrict__ b2) {
  int b = blockIdx.y;
  int r0 = blockIdx.x * 16;
  const float* emb = x + ((size_t)b * 64 + 63) * NA * DM;
  __shared__ float es[16][DM];
  __shared__ float red[16][8];
  int tid = threadIdx.x;
  int lane = tid & 31, warp = tid >> 5;

  for (int idx = tid; idx < 16 * DM; idx += 256) {
    int r = idx >> 8, d = idx & 255;
    es[r][d] = (r0 + r < NA) ? emb[(r0 + r) * DM + d] : 0.f;
  }
  __syncthreads();

  float acc[16];
  float bb = b1[tid];
#pragma unroll
  for (int r = 0; r < 16; r++) acc[r] = bb;

#pragma unroll 4
  for (int d = 0; d < DM; d++) {
    float w = w1[d * HID + tid];
#pragma unroll
    for (int r = 0; r < 16; r++) acc[r] = fmaf(es[r][d], w, acc[r]);
  }

  float wv = w2[tid];
#pragma unroll
  for (int r = 0; r < 16; r++) {
    float v = fmaxf(acc[r], 0.f) * wv;
#pragma unroll
    for (int o = 16; o; o >>= 1) v += __shfl_xor_sync(0xffffffffu, v, o);
    if (lane == 0) red[r][warp] = v;
  }
  __syncthreads();
  if (tid < 16) {
    float s = 0.f;
#pragma unroll
    for (int w = 0; w < 8; w++) s += red[tid][w];
    s += b2[0];
    float sp = fmaxf(s, 0.f) + log1pf(expf(-fabsf(s)));
    if (r0 + tid < NA) g_vols[b * NA + r0 + tid] = sp + 1e-6f;
  }
}

// ---------------------------------------------------------------------------
// pair MLP via mma.sync bf16 (2-way split, 3 passes), with register prefetch
// of the next K-chunk's gmem behind the current chunk's MMA phase.
// ---------------------------------------------------------------------------
#define OFF_A_HI 0
#define OFF_A_LO 5120
#define OFF_B_HI 10240
#define OFF_B_LO 30720
#define OFF_SI   51200
#define OFF_SJ   51456
#define OFF_B1   51712
#define OFF_W2   52736
#define OFF_RED  53760
#define SMEM_PAIR 54784

__global__ __launch_bounds__(256) void pair_mma_kernel(
    const float* __restrict__ x, const float* __restrict__ b1,
    const float* __restrict__ w2, const float* __restrict__ b2) {
  extern __shared__ char smem[];
  uint32_t sb = smem_u32(smem);
  int b = blockIdx.y, tile = blockIdx.x;
  int tid = threadIdx.x, lane = tid & 31, warp = tid >> 5;
  int wm = warp >> 2, wn = warp & 3;   // 2 x 4 warps
  const float* emb = x + ((size_t)b * 64 + 63) * NA * DM;

  int* si = (int*)(smem + OFF_SI);
  int* sj = (int*)(smem + OFF_SJ);
  float* b1s = (float*)(smem + OFF_B1);
  float* w2s = (float*)(smem + OFF_W2);
  float* red = (float*)(smem + OFF_RED);

  if (tid < PT) {
    int k = tile * PT + tid;
    if (k >= NPAIR) k = NPAIR - 1;
    int i = (int)((1.0f + sqrtf(1.0f + 8.0f * (float)k)) * 0.5f);
    while ((i * (i - 1)) / 2 > k) i--;
    while (((i + 1) * i) / 2 <= k) i++;
    si[tid] = i;
    sj[tid] = k - (i * (i - 1)) / 2;
  }
  b1s[tid] = b1[tid];
  w2s[tid] = w2[tid];
  __syncthreads();

  float acc[2][8][4];
#pragma unroll
  for (int mt = 0; mt < 2; mt++)
#pragma unroll
    for (int nt = 0; nt < 8; nt++)
#pragma unroll
      for (int e = 0; e < 4; e++) acc[mt][nt][e] = 0.f;

  // prefetch registers
  float2 Aea[4], Aeb[4];
  uint4 Bh[4], Bl[4];

  // prologue: load chunk 0
#pragma unroll
  for (int t = 0; t < 4; t++) {
    int idx = tid + t * 256;
    int row = idx >> 4, kk2 = idx & 15;
    Aea[t] = *(const float2*)(emb + si[row] * DM + 2 * kk2);
    Aeb[t] = *(const float2*)(emb + sj[row] * DM + 2 * kk2);
  }
#pragma unroll
  for (int t = 0; t < 4; t++) {
    int idx = tid + t * 256;
    int n = idx >> 2, kg = idx & 3;
    Bh[t] = *(const uint4*)(g_w1t_hi + n * DM + kg * 8);
    Bl[t] = *(const uint4*)(g_w1t_lo + n * DM + kg * 8);
  }

  for (int ch = 0; ch < 8; ch++) {
    // store prefetched chunk to smem (split/pack A on the fly)
#pragma unroll
    for (int t = 0; t < 4; t++) {
      int idx = tid + t * 256;
      int row = idx >> 4, kk2 = idx & 15;
      float p0 = Aea[t].x * Aeb[t].x, p1 = Aea[t].y * Aeb[t].y;
      __nv_bfloat16 h0 = __float2bfloat16(p0);
      __nv_bfloat16 h1 = __float2bfloat16(p1);
      __nv_bfloat16 l0 = __float2bfloat16(p0 - __bfloat162float(h0));
      __nv_bfloat16 l1 = __float2bfloat16(p1 - __bfloat162float(h1));
      uint32_t hp = ((uint32_t)*(uint16_t*)&h1 << 16) | *(uint16_t*)&h0;
      uint32_t lp = ((uint32_t)*(uint16_t*)&l1 << 16) | *(uint16_t*)&l0;
      *(uint32_t*)(smem + OFF_A_HI + row * 80 + kk2 * 4) = hp;
      *(uint32_t*)(smem + OFF_A_LO + row * 80 + kk2 * 4) = lp;
    }
#pragma unroll
    for (int t = 0; t < 4; t++) {
      int idx = tid + t * 256;
      int n = idx >> 2, kg = idx & 3;
      *(uint4*)(smem + OFF_B_HI + n * 80 + kg * 16) = Bh[t];
      *(uint4*)(smem + OFF_B_LO + n * 80 + kg * 16) = Bl[t];
    }
    __syncthreads();

    // issue next chunk's gmem loads (overlap with MMA below)
    if (ch < 7) {
      int k0 = (ch + 1) * 32;
#pragma unroll
      for (int t = 0; t < 4; t++) {
        int idx = tid + t * 256;
        int row = idx >> 4, kk2 = idx & 15;
        Aea[t] = *(const float2*)(emb + si[row] * DM + k0 + 2 * kk2);
        Aeb[t] = *(const float2*)(emb + sj[row] * DM + k0 + 2 * kk2);
      }
#pragma unroll
      for (int t = 0; t < 4; t++) {
        int idx = tid + t * 256;
        int n = idx >> 2, kg = idx & 3;
        Bh[t] = *(const uint4*)(g_w1t_hi + n * DM + k0 + kg * 8);
        Bl[t] = *(const uint4*)(g_w1t_lo + n * DM + k0 + kg * 8);
      }
    }

#pragma unroll
    for (int ks = 0; ks < 2; ks++) {
      uint32_t ah[2][4], al[2][4], bb[8][2];
      int arow = (lane & 7) + ((lane >> 3) & 1) * 8;
      int acolb = ks * 32 + ((lane >> 4) << 4);
#pragma unroll
      for (int mt = 0; mt < 2; mt++) {
        uint32_t ra = (uint32_t)((wm * 32 + mt * 16 + arow) * 80 + acolb);
        ldsm_x4(ah[mt], sb + OFF_A_HI + ra);
        ldsm_x4(al[mt], sb + OFF_A_LO + ra);
      }
      int bl_ = lane & 15;
      int brow = bl_ & 7;
      int bcolb = ks * 32 + ((bl_ >> 3) << 4);
#pragma unroll
      for (int nt = 0; nt < 8; nt++) {
        uint32_t rb = (uint32_t)((wn * 64 + nt * 8 + brow) * 80 + bcolb);
        ldsm_x2(bb[nt], sb + OFF_B_HI + rb);
      }
#pragma unroll
      for (int mt = 0; mt < 2; mt++)
#pragma unroll
        for (int nt = 0; nt < 8; nt++) mma16816(acc[mt][nt], ah[mt], bb[nt]);
#pragma unroll
      for (int mt = 0; mt < 2; mt++)
#pragma unroll
        for (int nt = 0; nt < 8; nt++) mma16816(acc[mt][nt], al[mt], bb[nt]);
#pragma unroll
      for (int nt = 0; nt < 8; nt++) {
        uint32_t rb = (uint32_t)((wn * 64 + nt * 8 + brow) * 80 + bcolb);
        ldsm_x2(bb[nt], sb + OFF_B_LO + rb);
      }
#pragma unroll
      for (int mt = 0; mt < 2; mt++)
#pragma unroll
        for (int nt = 0; nt < 8; nt++) mma16816(acc[mt][nt], ah[mt], bb[nt]);
    }
    __syncthreads();
  }

  // Epilogue
#pragma unroll
  for (int mt = 0; mt < 2; mt++) {
#pragma unroll
    for (int half = 0; half < 2; half++) {
      float s = 0.f;
#pragma unroll
      for (int nt = 0; nt < 8; nt++) {
        int col = wn * 64 + nt * 8 + 2 * (lane & 3);
        float h0 = acc[mt][nt][half * 2 + 0] + b1s[col];
        float h1 = acc[mt][nt][half * 2 + 1] + b1s[col + 1];
        s = fmaf(fmaxf(h0, 0.f), w2s[col], s);
        s = fmaf(fmaxf(h1, 0.f), w2s[col + 1], s);
      }
      s += __shfl_xor_sync(0xffffffffu, s, 1);
      s += __shfl_xor_sync(0xffffffffu, s, 2);
      if ((lane & 3) == 0) {
        int row = wm * 32 + mt * 16 + half * 8 + (lane >> 2);
        red[row * 4 + wn] = s;
      }
    }
  }
  __syncthreads();
  if (tid < PT) {
    int k = tile * PT + tid;
    if (k < NPAIR) {
      float s = red[tid * 4] + red[tid * 4 + 1] + red[tid * 4 + 2] +
                red[tid * 4 + 3] + b2[0];
      float t = tanhf(s);
      int i = si[tid], j = sj[tid];
      g_R[(size_t)b * NA * NA + i * NA + j] = t;
      g_R[(size_t)b * NA * NA + j * NA + i] = t;
    }
  }
}

// ---------------------------------------------------------------------------
// Split Jacobi: A-CTA (bid < 64) solves eigenvalues, logs rotations;
// V-CTA (bid >= 64) replays rotations into V, then reconstructs + epilogue.
// ---------------------------------------------------------------------------
#define EIG_THREADS 512
#define EIG_NW (EIG_THREADS / 32)
#define SMEM_EIG ((2 * NA * LDA + 320) * 4)

__global__ __launch_bounds__(EIG_THREADS) void eig_kernel(float* __restrict__ out) {
  extern __shared__ float sm[];
  int bid = blockIdx.x;
  int tid = threadIdx.x, lane = tid & 31, warp = tid >> 5;

  if (bid < BATCH) {
    // ================= A role =================
    int b = bid;
    float* A = sm;                  // NA*LDA
    float* red = sm + NA * LDA;     // 32
    const float* Rg = g_R + (size_t)b * NA * NA;

    for (int idx = tid; idx < NA * NA; idx += EIG_THREADS) {
      int r = idx / NA, c = idx - r * NA;
      A[r * LDA + c] = (r == c) ? 1.0f : Rg[idx];
    }
    __syncthreads();

    int seq = 0;
    for (int sweep = 0; sweep < MAX_SWEEPS; sweep++) {
      for (int round = 0; round < NA - 1; round++) {
        // rotations for this warp's pairs, in registers
        float rc_[4], rs_[4];
        int rp_[4], rq_[4];
#pragma unroll
        for (int t = 0; t < 4; t++) {
          int k = warp + 16 * t;
          rc_[t] = 1.f; rs_[t] = 0.f; rp_[t] = 0; rq_[t] = 0;
          if (k < NA / 2) {
            int p, q;
            pq_from(round, k, &p, &q);
            float app = A[p * LDA + p], aqq = A[q * LDA + q];
            float apq = A[p * LDA + q];
            float c = 1.f, s = 0.f;
            if (fabsf(apq) > 1e-7f) {
              float tau = (aqq - app) / (2.f * apq);
              float tt = copysignf(1.f / (fabsf(tau) + sqrtf(1.f + tau * tau)), tau);
              c = rsqrtf(1.f + tt * tt);
              s = tt * c;
            }
            rc_[t] = c; rs_[t] = s; rp_[t] = p; rq_[t] = q;
            if (lane == 0)
              g_rot[((size_t)b * ROT_ROUNDS + seq) * 64 + k] = make_float2(c, s);
          }
        }
        if (lane == 0) __threadfence();
        // column phase (A only)
#pragma unroll
        for (int t = 0; t < 4; t++) {
          float s = rs_[t];
          if (s != 0.f) {
            int p = rp_[t], q = rq_[t];
            float c = rc_[t];
            for (int r = lane; r < NA; r += 32) {
              float xp = A[r * LDA + p], xq = A[r * LDA + q];
              A[r * LDA + p] = c * xp - s * xq;
              A[r * LDA + q] = s * xp + c * xq;
            }
          }
        }
        __syncthreads();
        if (tid == 0) *(volatile int*)&g_flag[b] = seq + 1;
        // row phase
#pragma unroll
        for (int t = 0; t < 4; t++) {
          float s = rs_[t];
          if (s != 0.f) {
            int p = rp_[t], q = rq_[t];
            float c = rc_[t];
            for (int r = lane; r < NA; r += 32) {
              float xp = A[p * LDA + r], xq = A[q * LDA + r];
              A[p * LDA + r] = c * xp - s * xq;
              A[q * LDA + r] = s * xp + c * xq;
            }
          }
        }
        __syncthreads();
        seq++;
      }
      // convergence: off-diag Frobenius^2
      float part = 0.f;
      for (int idx = tid; idx < NA * NA; idx += EIG_THREADS) {
        int r = idx / NA, c = idx - r * NA;
        if (r != c) { float v = A[r * LDA + c]; part += v * v; }
      }
#pragma unroll
      for (int o = 16; o; o >>= 1) part += __shfl_xor_sync(0xffffffffu, part, o);
      if (lane == 0) red[warp] = part;
      __syncthreads();
      if (tid == 0) {
        float s = 0.f;
        for (int w = 0; w < EIG_NW; w++) s += red[w];
        red[0] = s;
      }
      __syncthreads();
      if (red[0] < 1e-8f) break;
      __syncthreads();
    }
    // publish eigenvalues + done
    if (tid < NA) g_evals[b * 128 + tid] = A[tid * LDA + tid];
    __syncthreads();
    if (tid == 0) {
      __threadfence();
      *(volatile int*)&g_done[b] = seq;
    }
  } else {
    // ================= V role =================
    int b = bid - BATCH;
    float* V = sm;                    // NA*LDA
    float* P = sm + NA * LDA;         // NA*LDA
    float* sq = P + NA * LDA;         // 128
    float* invs = sq + 128;           // 128
    int* vshare = (int*)(invs + 128); // 2

    for (int idx = tid; idx < NA * NA; idx += EIG_THREADS) {
      int r = idx / NA, c = idx - r * NA;
      V[r * LDA + c] = (r == c) ? 1.0f : 0.0f;
    }
    __syncthreads();

    int seq = 0;
    for (;;) {
      if (tid == 0) {
        int f, d;
        for (;;) {
          f = *(volatile int*)&g_flag[b];
          d = *(volatile int*)&g_done[b];
          if (f > seq || (d != 0 && d <= seq)) break;
        }
        __threadfence();
        vshare[0] = f;
        vshare[1] = d;
      }
      __syncthreads();
      int avail = vshare[0], done = vshare[1];
      if (done != 0 && seq >= done) break;
      for (; seq < avail; seq++) {
        int round = seq % (NA - 1);
#pragma unroll
        for (int t = 0; t < 4; t++) {
          int k = warp + 16 * t;
          if (k < NA / 2) {
            float2 cs = g_rot[((size_t)b * ROT_ROUNDS + seq) * 64 + k];
            if (cs.y != 0.f) {
              int p, q;
              pq_from(round, k, &p, &q);
              for (int r = lane; r < NA; r += 32) {
                float vp = V[r * LDA + p], vq = V[r * LDA + q];
                V[r * LDA + p] = cs.x * vp - cs.y * vq;
                V[r * LDA + q] = cs.y * vp + cs.x * vq;
              }
            }
          }
        }
        __syncthreads();
      }
    }
    __syncthreads();

    // finalize: scale columns by sqrt(clip(lambda))
    if (tid < NA) sq[tid] = sqrtf(fmaxf(g_evals[b * 128 + tid], 1e-4f));
    __syncthreads();
    for (int idx = tid; idx < NA * NA; idx += EIG_THREADS) {
      int r = idx / NA, c = idx - r * NA;
      V[r * LDA + c] *= sq[c];
    }
    __syncthreads();

    // R_psd = V' V'^T (triangular)
    const int NTRI = NA * (NA + 1) / 2;
    for (int idx = tid; idx < NTRI; idx += EIG_THREADS) {
      int i = (int)((sqrtf(8.f * (float)idx + 1.f) - 1.f) * 0.5f);
      while (i * (i + 1) / 2 > idx) i--;
      while ((i + 1) * (i + 2) / 2 <= idx) i++;
      int j = idx - i * (i + 1) / 2;
      const float* vi = V + i * LDA;
      const float* vj = V + j * LDA;
      float sum = 0.f;
#pragma unroll 4
      for (int k = 0; k < NA; k++) sum = fmaf(vi[k], vj[k], sum);
      P[i * LDA + j] = sum;
      P[j * LDA + i] = sum;
    }
    __syncthreads();

    if (tid < NA) {
      float d = P[tid * LDA + tid];
      invs[tid] = rsqrtf(fmaxf(d, 1e-6f));
    }
    __syncthreads();

    float* og = out + (size_t)b * NA * NA;
    const float* vl = g_vols + b * NA;
    for (int idx = tid; idx < NA * NA; idx += EIG_THREADS) {
      int r = idx / NA, c = idx - r * NA;
      og[idx] = vl[r] * vl[c] * invs[r] * invs[c] * P[r * LDA + c];
    }
  }
}

// ---------------------------------------------------------------------------
extern "C" void kernel_launch(void* const* d_in, const int* in_sizes, int n_in,
                              void* d_out, int out_size) {
  const float* x   = (const float*)d_in[0];
  const float* vw1 = (const float*)d_in[1];
  const float* vb1 = (const float*)d_in[2];
  const float* vw2 = (const float*)d_in[3];
  const float* vb2 = (const float*)d_in[4];
  const float* cw1 = (const float*)d_in[5];
  const float* cb1 = (const float*)d_in[6];
  const float* cw2 = (const float*)d_in[7];
  const float* cb2 = (const float*)d_in[8];
  float* out = (float*)d_out;

  zero_flags<<<1, 128>>>();
  prep_w1t<<<HID, DM>>>(cw1);
  vols_kernel<<<dim3(7, BATCH), 256>>>(x, vw1, vb1, vw2, vb2);

  cudaFuncSetAttribute(pair_mma_kernel,
                       cudaFuncAttributeMaxDynamicSharedMemorySize, SMEM_PAIR);
  pair_mma_kernel<<<dim3(PTILES, BATCH), 256, SMEM_PAIR>>>(x, cb1, cw2, cb2);

  cudaFuncSetAttribute(eig_kernel, cudaFuncAttributeMaxDynamicSharedMemorySize,
                       SMEM_EIG);
  eig_kernel<<<2 * BATCH, EIG_THREADS, SMEM_EIG>>>(out);
}

// round 8
// speedup vs baseline: 1.0314x; 1.0314x over previous
#include <cuda_runtime.h>
#include <cuda_bf16.h>
#include <math.h>
#include <stdint.h>

#define NA 100
#define DM 256
#define HID 256
#define BATCH 64
#define NPAIR 4950
#define LDA 101
#define PT 64           // pairs per CTA tile
#define PTILES 78       // ceil(4950/64)

// ---------------- device scratch (no allocation allowed) ----------------
__device__ float g_R[BATCH * NA * NA];
__device__ float g_vols[BATCH * NA];
__device__ __nv_bfloat16 g_w1t_hi[HID * DM];  // [n][k] K-major
__device__ __nv_bfloat16 g_w1t_lo[HID * DM];

__device__ __forceinline__ uint32_t smem_u32(const void* p) {
  uint32_t a;
  asm("{ .reg .u64 t; cvta.to.shared.u64 t, %1; cvt.u32.u64 %0, t; }"
      : "=r"(a) : "l"(p));
  return a;
}
__device__ __forceinline__ void ldsm_x4(uint32_t (&r)[4], uint32_t addr) {
  asm volatile(
      "ldmatrix.sync.aligned.m8n8.x4.shared.b16 {%0,%1,%2,%3}, [%4];"
      : "=r"(r[0]), "=r"(r[1]), "=r"(r[2]), "=r"(r[3]) : "r"(addr));
}
__device__ __forceinline__ void ldsm_x2(uint32_t (&r)[2], uint32_t addr) {
  asm volatile(
      "ldmatrix.sync.aligned.m8n8.x2.shared.b16 {%0,%1}, [%2];"
      : "=r"(r[0]), "=r"(r[1]) : "r"(addr));
}
__device__ __forceinline__ void mma16816(float (&d)[4], const uint32_t (&a)[4],
                                         const uint32_t (&b)[2]) {
  asm volatile(
      "mma.sync.aligned.m16n8k16.row.col.f32.bf16.bf16.f32 "
      "{%0,%1,%2,%3}, {%4,%5,%6,%7}, {%8,%9}, {%0,%1,%2,%3};"
      : "+f"(d[0]), "+f"(d[1]), "+f"(d[2]), "+f"(d[3])
      : "r"(a[0]), "r"(a[1]), "r"(a[2]), "r"(a[3]), "r"(b[0]), "r"(b[1]));
}
__device__ __forceinline__ void pq_from(int round, int k, int* pp, int* qq) {
  const int m = NA - 1;
  int p, q;
  if (k == 0) { p = m; q = round % m; }
  else { p = (round + k) % m; q = (round - k + m) % m; }
  if (p > q) { int t = p; p = q; q = t; }
  *pp = p; *qq = q;
}

// ---------------------------------------------------------------------------
__global__ void prep_w1t(const float* __restrict__ w1) {
  int n = blockIdx.x, k = threadIdx.x;
  float v = w1[k * HID + n];
  __nv_bfloat16 h = __float2bfloat16(v);
  float r = v - __bfloat162float(h);
  g_w1t_hi[n * DM + k] = h;
  g_w1t_lo[n * DM + k] = __float2bfloat16(r);
}

// ---------------------------------------------------------------------------
__global__ __launch_bounds__(256) void vols_kernel(
    const float* __restrict__ x, const float* __restrict__ w1,
    const float* __restrict__ b1, const float* __restrict__ w2,
    const float* __restrict__ b2) {
  int b = blockIdx.y;
  int r0 = blockIdx.x * 16;
  const float* emb = x + ((size_t)b * 64 + 63) * NA * DM;
  __shared__ float es[16][DM];
  __shared__ float red[16][8];
  int tid = threadIdx.x;
  int lane = tid & 31, warp = tid >> 5;

  for (int idx = tid; idx < 16 * DM; idx += 256) {
    int r = idx >> 8, d = idx & 255;
    es[r][d] = (r0 + r < NA) ? emb[(r0 + r) * DM + d] : 0.f;
  }
  __syncthreads();

  float acc[16];
  float bb = b1[tid];
#pragma unroll
  for (int r = 0; r < 16; r++) acc[r] = bb;

#pragma unroll 4
  for (int d = 0; d < DM; d++) {
    float w = w1[d * HID + tid];
#pragma unroll
    for (int r = 0; r < 16; r++) acc[r] = fmaf(es[r][d], w, acc[r]);
  }

  float wv = w2[tid];
#pragma unroll
  for (int r = 0; r < 16; r++) {
    float v = fmaxf(acc[r], 0.f) * wv;
#pragma unroll
    for (int o = 16; o; o >>= 1) v += __shfl_xor_sync(0xffffffffu, v, o);
    if (lane == 0) red[r][warp] = v;
  }
  __syncthreads();
  if (tid < 16) {
    float s = 0.f;
#pragma unroll
    for (int w = 0; w < 8; w++) s += red[tid][w];
    s += b2[0];
    float sp = fmaxf(s, 0.f) + log1pf(expf(-fabsf(s)));
    if (r0 + tid < NA) g_vols[b * NA + r0 + tid] = sp + 1e-6f;
  }
}

// ---------------------------------------------------------------------------
// pair MLP via mma.sync bf16 (2-way split, 3 passes), 512 threads / 16 warps
// (4M x 4N, warp tile 16x64) -> ~110 regs, 16 resident warps. Register
// prefetch of next K-chunk overlaps gmem with MMA.
// ---------------------------------------------------------------------------
#define OFF_A_HI 0
#define OFF_A_LO 5120
#define OFF_B_HI 10240
#define OFF_B_LO 30720
#define OFF_SI   51200
#define OFF_SJ   51456
#define OFF_B1   51712
#define OFF_W2   52736
#define OFF_RED  53760
#define SMEM_PAIR 54784

__global__ __launch_bounds__(512) void pair_mma_kernel(
    const float* __restrict__ x, const float* __restrict__ b1,
    const float* __restrict__ w2, const float* __restrict__ b2) {
  extern __shared__ char smem[];
  uint32_t sb = smem_u32(smem);
  int b = blockIdx.y, tile = blockIdx.x;
  int tid = threadIdx.x, lane = tid & 31, warp = tid >> 5;
  int wm = warp >> 2, wn = warp & 3;   // 4 x 4 warps, warp tile 16 x 64
  const float* emb = x + ((size_t)b * 64 + 63) * NA * DM;

  int* si = (int*)(smem + OFF_SI);
  int* sj = (int*)(smem + OFF_SJ);
  float* b1s = (float*)(smem + OFF_B1);
  float* w2s = (float*)(smem + OFF_W2);
  float* red = (float*)(smem + OFF_RED);

  if (tid < PT) {
    int k = tile * PT + tid;
    if (k >= NPAIR) k = NPAIR - 1;
    int i = (int)((1.0f + sqrtf(1.0f + 8.0f * (float)k)) * 0.5f);
    while ((i * (i - 1)) / 2 > k) i--;
    while (((i + 1) * i) / 2 <= k) i++;
    si[tid] = i;
    sj[tid] = k - (i * (i - 1)) / 2;
  }
  if (tid < HID) {
    b1s[tid] = b1[tid];
    w2s[tid] = w2[tid];
  }
  __syncthreads();

  float acc[8][4];
#pragma unroll
  for (int nt = 0; nt < 8; nt++)
#pragma unroll
    for (int e = 0; e < 4; e++) acc[nt][e] = 0.f;

  // prefetch registers (per-thread halved vs 256-thread version)
  float2 Aea[2], Aeb[2];
  uint4 Bh[2], Bl[2];

#pragma unroll
  for (int t = 0; t < 2; t++) {
    int idx = tid + t * 512;
    int row = idx >> 4, kk2 = idx & 15;
    Aea[t] = *(const float2*)(emb + si[row] * DM + 2 * kk2);
    Aeb[t] = *(const float2*)(emb + sj[row] * DM + 2 * kk2);
  }
#pragma unroll
  for (int t = 0; t < 2; t++) {
    int idx = tid + t * 512;
    int n = idx >> 2, kg = idx & 3;
    Bh[t] = *(const uint4*)(g_w1t_hi + n * DM + kg * 8);
    Bl[t] = *(const uint4*)(g_w1t_lo + n * DM + kg * 8);
  }

  for (int ch = 0; ch < 8; ch++) {
    // stage prefetched chunk into smem
#pragma unroll
    for (int t = 0; t < 2; t++) {
      int idx = tid + t * 512;
      int row = idx >> 4, kk2 = idx & 15;
      float p0 = Aea[t].x * Aeb[t].x, p1 = Aea[t].y * Aeb[t].y;
      __nv_bfloat16 h0 = __float2bfloat16(p0);
      __nv_bfloat16 h1 = __float2bfloat16(p1);
      __nv_bfloat16 l0 = __float2bfloat16(p0 - __bfloat162float(h0));
      __nv_bfloat16 l1 = __float2bfloat16(p1 - __bfloat162float(h1));
      uint32_t hp = ((uint32_t)*(uint16_t*)&h1 << 16) | *(uint16_t*)&h0;
      uint32_t lp = ((uint32_t)*(uint16_t*)&l1 << 16) | *(uint16_t*)&l0;
      *(uint32_t*)(smem + OFF_A_HI + row * 80 + kk2 * 4) = hp;
      *(uint32_t*)(smem + OFF_A_LO + row * 80 + kk2 * 4) = lp;
    }
#pragma unroll
    for (int t = 0; t < 2; t++) {
      int idx = tid + t * 512;
      int n = idx >> 2, kg = idx & 3;
      *(uint4*)(smem + OFF_B_HI + n * 80 + kg * 16) = Bh[t];
      *(uint4*)(smem + OFF_B_LO + n * 80 + kg * 16) = Bl[t];
    }
    __syncthreads();

    // prefetch next chunk (overlaps the MMA phase)
    if (ch < 7) {
      int k0 = (ch + 1) * 32;
#pragma unroll
      for (int t = 0; t < 2; t++) {
        int idx = tid + t * 512;
        int row = idx >> 4, kk2 = idx & 15;
        Aea[t] = *(const float2*)(emb + si[row] * DM + k0 + 2 * kk2);
        Aeb[t] = *(const float2*)(emb + sj[row] * DM + k0 + 2 * kk2);
      }
#pragma unroll
      for (int t = 0; t < 2; t++) {
        int idx = tid + t * 512;
        int n = idx >> 2, kg = idx & 3;
        Bh[t] = *(const uint4*)(g_w1t_hi + n * DM + k0 + kg * 8);
        Bl[t] = *(const uint4*)(g_w1t_lo + n * DM + k0 + kg * 8);
      }
    }

#pragma unroll
    for (int ks = 0; ks < 2; ks++) {
      uint32_t ah[4], al[4], bb[8][2];
      int arow = (lane & 7) + ((lane >> 3) & 1) * 8;
      int acolb = ks * 32 + ((lane >> 4) << 4);
      uint32_t ra = (uint32_t)((wm * 16 + arow) * 80 + acolb);
      ldsm_x4(ah, sb + OFF_A_HI + ra);
      ldsm_x4(al, sb + OFF_A_LO + ra);
      int bl_ = lane & 15;
      int brow = bl_ & 7;
      int bcolb = ks * 32 + ((bl_ >> 3) << 4);
#pragma unroll
      for (int nt = 0; nt < 8; nt++) {
        uint32_t rb = (uint32_t)((wn * 64 + nt * 8 + brow) * 80 + bcolb);
        ldsm_x2(bb[nt], sb + OFF_B_HI + rb);
      }
#pragma unroll
      for (int nt = 0; nt < 8; nt++) mma16816(acc[nt], ah, bb[nt]);
#pragma unroll
      for (int nt = 0; nt < 8; nt++) mma16816(acc[nt], al, bb[nt]);
#pragma unroll
      for (int nt = 0; nt < 8; nt++) {
        uint32_t rb = (uint32_t)((wn * 64 + nt * 8 + brow) * 80 + bcolb);
        ldsm_x2(bb[nt], sb + OFF_B_LO + rb);
      }
#pragma unroll
      for (int nt = 0; nt < 8; nt++) mma16816(acc[nt], ah, bb[nt]);
    }
    __syncthreads();
  }

  // Epilogue: relu(h + b1) . w2, quad shuffle-reduce, cross-warp reduce
#pragma unroll
  for (int half = 0; half < 2; half++) {
    float s = 0.f;
#pragma unroll
    for (int nt = 0; nt < 8; nt++) {
      int col = wn * 64 + nt * 8 + 2 * (lane & 3);
      float h0 = acc[nt][half * 2 + 0] + b1s[col];
      float h1 = acc[nt][half * 2 + 1] + b1s[col + 1];
      s = fmaf(fmaxf(h0, 0.f), w2s[col], s);
      s = fmaf(fmaxf(h1, 0.f), w2s[col + 1], s);
    }
    s += __shfl_xor_sync(0xffffffffu, s, 1);
    s += __shfl_xor_sync(0xffffffffu, s, 2);
    if ((lane & 3) == 0) {
      int row = wm * 16 + half * 8 + (lane >> 2);
      red[row * 4 + wn] = s;
    }
  }
  __syncthreads();
  if (tid < PT) {
    int k = tile * PT + tid;
    if (k < NPAIR) {
      float s = red[tid * 4] + red[tid * 4 + 1] + red[tid * 4 + 2] +
                red[tid * 4 + 3] + b2[0];
      float t = tanhf(s);
      int i = si[tid], j = sj[tid];
      g_R[(size_t)b * NA * NA + i * NA + j] = t;
      g_R[(size_t)b * NA * NA + j * NA + i] = t;
    }
  }
}

// ---------------------------------------------------------------------------
// Monolithic batched Jacobi eig (one CTA per matrix) with per-warp register
// rotations (2 barriers/round) + rotation-skip. Then reconstruct + epilogue.
// ---------------------------------------------------------------------------
#define EIG_THREADS 512
#define EIG_NW (EIG_THREADS / 32)
#define MAX_SWEEPS 16
#define SMEM_EIG ((2 * NA * LDA + 288) * 4)

__global__ __launch_bounds__(EIG_THREADS) void eig_kernel(float* __restrict__ out) {
  extern __shared__ float sm[];
  float* A = sm;                    // NA*LDA
  float* V = A + NA * LDA;          // NA*LDA
  float* sq = V + NA * LDA;         // 128
  float* invs = sq + 128;           // 128
  float* red = invs + 128;          // 32

  int b = blockIdx.x;
  int tid = threadIdx.x;
  int lane = tid & 31, warp = tid >> 5;
  const float* Rg = g_R + (size_t)b * NA * NA;

  for (int idx = tid; idx < NA * NA; idx += EIG_THREADS) {
    int r = idx / NA, c = idx - r * NA;
    A[r * LDA + c] = (r == c) ? 1.0f : Rg[idx];
    V[r * LDA + c] = (r == c) ? 1.0f : 0.0f;
  }
  __syncthreads();

  for (int sweep = 0; sweep < MAX_SWEEPS; sweep++) {
    for (int round = 0; round < NA - 1; round++) {
      // rotations for this warp's pairs, computed in registers (broadcast LDS)
      float rc_[4], rs_[4];
      int rp_[4], rq_[4];
#pragma unroll
      for (int t = 0; t < 4; t++) {
        int k = warp + 16 * t;
        rc_[t] = 1.f; rs_[t] = 0.f; rp_[t] = 0; rq_[t] = 0;
        if (k < NA / 2) {
          int p, q;
          pq_from(round, k, &p, &q);
          float app = A[p * LDA + p], aqq = A[q * LDA + q];
          float apq = A[p * LDA + q];
          if (fabsf(apq) > 1e-7f) {
            float tau = (aqq - app) / (2.f * apq);
            float tt = copysignf(1.f / (fabsf(tau) + sqrtf(1.f + tau * tau)), tau);
            float c = rsqrtf(1.f + tt * tt);
            rc_[t] = c; rs_[t] = tt * c;
          }
          rp_[t] = p; rq_[t] = q;
        }
      }
      // column phase: A <- A J, V <- V J
#pragma unroll
      for (int t = 0; t < 4; t++) {
        float s = rs_[t];
        if (s != 0.f) {
          int p = rp_[t], q = rq_[t];
          float c = rc_[t];
          for (int r = lane; r < NA; r += 32) {
            float xp = A[r * LDA + p], xq = A[r * LDA + q];
            A[r * LDA + p] = c * xp - s * xq;
            A[r * LDA + q] = s * xp + c * xq;
            float vp = V[r * LDA + p], vq = V[r * LDA + q];
            V[r * LDA + p] = c * vp - s * vq;
            V[r * LDA + q] = s * vp + c * vq;
          }
        }
      }
      __syncthreads();
      // row phase: A <- J^T A
#pragma unroll
      for (int t = 0; t < 4; t++) {
        float s = rs_[t];
        if (s != 0.f) {
          int p = rp_[t], q = rq_[t];
          float c = rc_[t];
          for (int r = lane; r < NA; r += 32) {
            float xp = A[p * LDA + r], xq = A[q * LDA + r];
            A[p * LDA + r] = c * xp - s * xq;
            A[q * LDA + r] = s * xp + c * xq;
          }
        }
      }
      __syncthreads();
    }
    // convergence: off-diag Frobenius^2
    float part = 0.f;
    for (int idx = tid; idx < NA * NA; idx += EIG_THREADS) {
      int r = idx / NA, c = idx - r * NA;
      if (r != c) { float v = A[r * LDA + c]; part += v * v; }
    }
#pragma unroll
    for (int o = 16; o; o >>= 1) part += __shfl_xor_sync(0xffffffffu, part, o);
    if (lane == 0) red[warp] = part;
    __syncthreads();
    if (tid == 0) {
      float s = 0.f;
      for (int w = 0; w < EIG_NW; w++) s += red[w];
      red[0] = s;
    }
    __syncthreads();
    if (red[0] < 1e-8f) break;
    __syncthreads();
  }

  if (tid < NA) {
    float lam = A[tid * LDA + tid];
    sq[tid] = sqrtf(fmaxf(lam, 1e-4f));
  }
  __syncthreads();
  for (int idx = tid; idx < NA * NA; idx += EIG_THREADS) {
    int r = idx / NA, c = idx - r * NA;
    V[r * LDA + c] *= sq[c];
  }
  __syncthreads();

  // R_psd = V' V'^T (triangular), into A
  const int NTRI = NA * (NA + 1) / 2;
  for (int idx = tid; idx < NTRI; idx += EIG_THREADS) {
    int i = (int)((sqrtf(8.f * (float)idx + 1.f) - 1.f) * 0.5f);
    while (i * (i + 1) / 2 > idx) i--;
    while ((i + 1) * (i + 2) / 2 <= idx) i++;
    int j = idx - i * (i + 1) / 2;
    const float* vi = V + i * LDA;
    const float* vj = V + j * LDA;
    float sum = 0.f;
#pragma unroll 4
    for (int k = 0; k < NA; k++) sum = fmaf(vi[k], vj[k], sum);
    A[i * LDA + j] = sum;
    A[j * LDA + i] = sum;
  }
  __syncthreads();

  if (tid < NA) {
    float d = A[tid * LDA + tid];
    invs[tid] = rsqrtf(fmaxf(d, 1e-6f));
  }
  __syncthreads();

  float* og = out + (size_t)b * NA * NA;
  const float* vl = g_vols + b * NA;
  for (int idx = tid; idx < NA * NA; idx += EIG_THREADS) {
    int r = idx / NA, c = idx - r * NA;
    og[idx] = vl[r] * vl[c] * invs[r] * invs[c] * A[r * LDA + c];
  }
}

// ---------------------------------------------------------------------------
extern "C" void kernel_launch(void* const* d_in, const int* in_sizes, int n_in,
                              void* d_out, int out_size) {
  const float* x   = (const float*)d_in[0];
  const float* vw1 = (const float*)d_in[1];
  const float* vb1 = (const float*)d_in[2];
  const float* vw2 = (const float*)d_in[3];
  const float* vb2 = (const float*)d_in[4];
  const float* cw1 = (const float*)d_in[5];
  const float* cb1 = (const float*)d_in[6];
  const float* cw2 = (const float*)d_in[7];
  const float* cb2 = (const float*)d_in[8];
  float* out = (float*)d_out;

  prep_w1t<<<HID, DM>>>(cw1);
  vols_kernel<<<dim3(7, BATCH), 256>>>(x, vw1, vb1, vw2, vb2);

  cudaFuncSetAttribute(pair_mma_kernel,
                       cudaFuncAttributeMaxDynamicSharedMemorySize, SMEM_PAIR);
  pair_mma_kernel<<<dim3(PTILES, BATCH), 512, SMEM_PAIR>>>(x, cb1, cw2, cb2);

  cudaFuncSetAttribute(eig_kernel, cudaFuncAttributeMaxDynamicSharedMemorySize,
                       SMEM_EIG);
  eig_kernel<<<BATCH, EIG_THREADS, SMEM_EIG>>>(out);
}

// round 10
// speedup vs baseline: 2.5279x; 2.4510x over previous
#include <cuda_runtime.h>
#include <cuda_bf16.h>
#include <math.h>
#include <stdint.h>

#define NA 100
#define DM 256
#define HID 256
#define BATCH 64
#define NPAIR 4950
#define PT 64           // pairs per CTA tile
#define PTILES 78       // ceil(4950/64)

// ---------------- device scratch (no allocation allowed) ----------------
__device__ float g_R[BATCH * NA * NA];
__device__ float g_vols[BATCH * NA];
__device__ __nv_bfloat16 g_w1t_hi[HID * DM];  // [n][k] K-major
__device__ __nv_bfloat16 g_w1t_lo[HID * DM];

__device__ __forceinline__ uint32_t smem_u32(const void* p) {
  uint32_t a;
  asm("{ .reg .u64 t; cvta.to.shared.u64 t, %1; cvt.u32.u64 %0, t; }"
      : "=r"(a) : "l"(p));
  return a;
}
__device__ __forceinline__ void ldsm_x4(uint32_t (&r)[4], uint32_t addr) {
  asm volatile(
      "ldmatrix.sync.aligned.m8n8.x4.shared.b16 {%0,%1,%2,%3}, [%4];"
      : "=r"(r[0]), "=r"(r[1]), "=r"(r[2]), "=r"(r[3]) : "r"(addr));
}
__device__ __forceinline__ void ldsm_x2(uint32_t (&r)[2], uint32_t addr) {
  asm volatile(
      "ldmatrix.sync.aligned.m8n8.x2.shared.b16 {%0,%1}, [%2];"
      : "=r"(r[0]), "=r"(r[1]) : "r"(addr));
}
__device__ __forceinline__ void mma16816(float (&d)[4], const uint32_t (&a)[4],
                                         const uint32_t (&b)[2]) {
  asm volatile(
      "mma.sync.aligned.m16n8k16.row.col.f32.bf16.bf16.f32 "
      "{%0,%1,%2,%3}, {%4,%5,%6,%7}, {%8,%9}, {%0,%1,%2,%3};"
      : "+f"(d[0]), "+f"(d[1]), "+f"(d[2]), "+f"(d[3])
      : "r"(a[0]), "r"(a[1]), "r"(a[2]), "r"(a[3]), "r"(b[0]), "r"(b[1]));
}
__device__ __forceinline__ uint32_t pack_bf16(float a, float b) {
  __nv_bfloat16 h0 = __float2bfloat16(a), h1 = __float2bfloat16(b);
  return ((uint32_t)*(uint16_t*)&h1 << 16) | *(uint16_t*)&h0;
}

// ---------------------------------------------------------------------------
__global__ void prep_w1t(const float* __restrict__ w1) {
  int n = blockIdx.x, k = threadIdx.x;
  float v = w1[k * HID + n];
  __nv_bfloat16 h = __float2bfloat16(v);
  float r = v - __bfloat162float(h);
  g_w1t_hi[n * DM + k] = h;
  g_w1t_lo[n * DM + k] = __float2bfloat16(r);
}

// ---------------------------------------------------------------------------
__global__ __launch_bounds__(256) void vols_kernel(
    const float* __restrict__ x, const float* __restrict__ w1,
    const float* __restrict__ b1, const float* __restrict__ w2,
    const float* __restrict__ b2) {
  int b = blockIdx.y;
  int r0 = blockIdx.x * 16;
  const float* emb = x + ((size_t)b * 64 + 63) * NA * DM;
  __shared__ float es[16][DM];
  __shared__ float red[16][8];
  int tid = threadIdx.x;
  int lane = tid & 31, warp = tid >> 5;

  for (int idx = tid; idx < 16 * DM; idx += 256) {
    int r = idx >> 8, d = idx & 255;
    es[r][d] = (r0 + r < NA) ? emb[(r0 + r) * DM + d] : 0.f;
  }
  __syncthreads();

  float acc[16];
  float bb = b1[tid];
#pragma unroll
  for (int r = 0; r < 16; r++) acc[r] = bb;

#pragma unroll 4
  for (int d = 0; d < DM; d++) {
    float w = w1[d * HID + tid];
#pragma unroll
    for (int r = 0; r < 16; r++) acc[r] = fmaf(es[r][d], w, acc[r]);
  }

  float wv = w2[tid];
#pragma unroll
  for (int r = 0; r < 16; r++) {
    float v = fmaxf(acc[r], 0.f) * wv;
#pragma unroll
    for (int o = 16; o; o >>= 1) v += __shfl_xor_sync(0xffffffffu, v, o);
    if (lane == 0) red[r][warp] = v;
  }
  __syncthreads();
  if (tid < 16) {
    float s = 0.f;
#pragma unroll
    for (int w = 0; w < 8; w++) s += red[tid][w];
    s += b2[0];
    float sp = fmaxf(s, 0.f) + log1pf(expf(-fabsf(s)));
    if (r0 + tid < NA) g_vols[b * NA + r0 + tid] = sp + 1e-6f;
  }
}

// ---------------------------------------------------------------------------
// pair MLP via mma.sync bf16 (2-way split, 3 passes), 256 threads,
// warp tile 32x64, register prefetch of next K-chunk. (round-7 measured)
// ---------------------------------------------------------------------------
#define OFF_A_HI 0
#define OFF_A_LO 5120
#define OFF_B_HI 10240
#define OFF_B_LO 30720
#define OFF_SI   51200
#define OFF_SJ   51456
#define OFF_B1   51712
#define OFF_W2   52736
#define OFF_RED  53760
#define SMEM_PAIR 54784

__global__ __launch_bounds__(256) void pair_mma_kernel(
    const float* __restrict__ x, const float* __restrict__ b1,
    const float* __restrict__ w2, const float* __restrict__ b2) {
  extern __shared__ char smem[];
  uint32_t sb = smem_u32(smem);
  int b = blockIdx.y, tile = blockIdx.x;
  int tid = threadIdx.x, lane = tid & 31, warp = tid >> 5;
  int wm = warp >> 2, wn = warp & 3;   // 2 x 4 warps
  const float* emb = x + ((size_t)b * 64 + 63) * NA * DM;

  int* si = (int*)(smem + OFF_SI);
  int* sj = (int*)(smem + OFF_SJ);
  float* b1s = (float*)(smem + OFF_B1);
  float* w2s = (float*)(smem + OFF_W2);
  float* red = (float*)(smem + OFF_RED);

  if (tid < PT) {
    int k = tile * PT + tid;
    if (k >= NPAIR) k = NPAIR - 1;
    int i = (int)((1.0f + sqrtf(1.0f + 8.0f * (float)k)) * 0.5f);
    while ((i * (i - 1)) / 2 > k) i--;
    while (((i + 1) * i) / 2 <= k) i++;
    si[tid] = i;
    sj[tid] = k - (i * (i - 1)) / 2;
  }
  b1s[tid] = b1[tid];
  w2s[tid] = w2[tid];
  __syncthreads();

  float acc[2][8][4];
#pragma unroll
  for (int mt = 0; mt < 2; mt++)
#pragma unroll
    for (int nt = 0; nt < 8; nt++)
#pragma unroll
      for (int e = 0; e < 4; e++) acc[mt][nt][e] = 0.f;

  float2 Aea[4], Aeb[4];
  uint4 Bh[4], Bl[4];

#pragma unroll
  for (int t = 0; t < 4; t++) {
    int idx = tid + t * 256;
    int row = idx >> 4, kk2 = idx & 15;
    Aea[t] = *(const float2*)(emb + si[row] * DM + 2 * kk2);
    Aeb[t] = *(const float2*)(emb + sj[row] * DM + 2 * kk2);
  }
#pragma unroll
  for (int t = 0; t < 4; t++) {
    int idx = tid + t * 256;
    int n = idx >> 2, kg = idx & 3;
    Bh[t] = *(const uint4*)(g_w1t_hi + n * DM + kg * 8);
    Bl[t] = *(const uint4*)(g_w1t_lo + n * DM + kg * 8);
  }

  for (int ch = 0; ch < 8; ch++) {
#pragma unroll
    for (int t = 0; t < 4; t++) {
      int idx = tid + t * 256;
      int row = idx >> 4, kk2 = idx & 15;
      float p0 = Aea[t].x * Aeb[t].x, p1 = Aea[t].y * Aeb[t].y;
      __nv_bfloat16 h0 = __float2bfloat16(p0);
      __nv_bfloat16 h1 = __float2bfloat16(p1);
      __nv_bfloat16 l0 = __float2bfloat16(p0 - __bfloat162float(h0));
      __nv_bfloat16 l1 = __float2bfloat16(p1 - __bfloat162float(h1));
      uint32_t hp = ((uint32_t)*(uint16_t*)&h1 << 16) | *(uint16_t*)&h0;
      uint32_t lp = ((uint32_t)*(uint16_t*)&l1 << 16) | *(uint16_t*)&l0;
      *(uint32_t*)(smem + OFF_A_HI + row * 80 + kk2 * 4) = hp;
      *(uint32_t*)(smem + OFF_A_LO + row * 80 + kk2 * 4) = lp;
    }
#pragma unroll
    for (int t = 0; t < 4; t++) {
      int idx = tid + t * 256;
      int n = idx >> 2, kg = idx & 3;
      *(uint4*)(smem + OFF_B_HI + n * 80 + kg * 16) = Bh[t];
      *(uint4*)(smem + OFF_B_LO + n * 80 + kg * 16) = Bl[t];
    }
    __syncthreads();

    if (ch < 7) {
      int k0 = (ch + 1) * 32;
#pragma unroll
      for (int t = 0; t < 4; t++) {
        int idx = tid + t * 256;
        int row = idx >> 4, kk2 = idx & 15;
        Aea[t] = *(const float2*)(emb + si[row] * DM + k0 + 2 * kk2);
        Aeb[t] = *(const float2*)(emb + sj[row] * DM + k0 + 2 * kk2);
      }
#pragma unroll
      for (int t = 0; t < 4; t++) {
        int idx = tid + t * 256;
        int n = idx >> 2, kg = idx & 3;
        Bh[t] = *(const uint4*)(g_w1t_hi + n * DM + k0 + kg * 8);
        Bl[t] = *(const uint4*)(g_w1t_lo + n * DM + k0 + kg * 8);
      }
    }

#pragma unroll
    for (int ks = 0; ks < 2; ks++) {
      uint32_t ah[2][4], al[2][4], bb[8][2];
      int arow = (lane & 7) + ((lane >> 3) & 1) * 8;
      int acolb = ks * 32 + ((lane >> 4) << 4);
#pragma unroll
      for (int mt = 0; mt < 2; mt++) {
        uint32_t ra = (uint32_t)((wm * 32 + mt * 16 + arow) * 80 + acolb);
        ldsm_x4(ah[mt], sb + OFF_A_HI + ra);
        ldsm_x4(al[mt], sb + OFF_A_LO + ra);
      }
      int bl_ = lane & 15;
      int brow = bl_ & 7;
      int bcolb = ks * 32 + ((bl_ >> 3) << 4);
#pragma unroll
      for (int nt = 0; nt < 8; nt++) {
        uint32_t rb = (uint32_t)((wn * 64 + nt * 8 + brow) * 80 + bcolb);
        ldsm_x2(bb[nt], sb + OFF_B_HI + rb);
      }
#pragma unroll
      for (int mt = 0; mt < 2; mt++)
#pragma unroll
        for (int nt = 0; nt < 8; nt++) mma16816(acc[mt][nt], ah[mt], bb[nt]);
#pragma unroll
      for (int mt = 0; mt < 2; mt++)
#pragma unroll
        for (int nt = 0; nt < 8; nt++) mma16816(acc[mt][nt], al[mt], bb[nt]);
#pragma unroll
      for (int nt = 0; nt < 8; nt++) {
        uint32_t rb = (uint32_t)((wn * 64 + nt * 8 + brow) * 80 + bcolb);
        ldsm_x2(bb[nt], sb + OFF_B_LO + rb);
      }
#pragma unroll
      for (int mt = 0; mt < 2; mt++)
#pragma unroll
        for (int nt = 0; nt < 8; nt++) mma16816(acc[mt][nt], ah[mt], bb[nt]);
    }
    __syncthreads();
  }

#pragma unroll
  for (int mt = 0; mt < 2; mt++) {
#pragma unroll
    for (int half = 0; half < 2; half++) {
      float s = 0.f;
#pragma unroll
      for (int nt = 0; nt < 8; nt++) {
        int col = wn * 64 + nt * 8 + 2 * (lane & 3);
        float h0 = acc[mt][nt][half * 2 + 0] + b1s[col];
        float h1 = acc[mt][nt][half * 2 + 1] + b1s[col + 1];
        s = fmaf(fmaxf(h0, 0.f), w2s[col], s);
        s = fmaf(fmaxf(h1, 0.f), w2s[col + 1], s);
      }
      s += __shfl_xor_sync(0xffffffffu, s, 1);
      s += __shfl_xor_sync(0xffffffffu, s, 2);
      if ((lane & 3) == 0) {
        int row = wm * 32 + mt * 16 + half * 8 + (lane >> 2);
        red[row * 4 + wn] = s;
      }
    }
  }
  __syncthreads();
  if (tid < PT) {
    int k = tile * PT + tid;
    if (k < NPAIR) {
      float s = red[tid * 4] + red[tid * 4 + 1] + red[tid * 4 + 2] +
                red[tid * 4 + 3] + b2[0];
      float t = tanhf(s);
      int i = si[tid], j = sj[tid];
      g_R[(size_t)b * NA * NA + i * NA + j] = t;
      g_R[(size_t)b * NA * NA + j * NA + i] = t;
    }
  }
}

// ---------------------------------------------------------------------------
// PSD projection via Newton-Schulz matrix sign (NO eigensolver), with
// explicit per-iteration SYMMETRIZATION (kills imaginary-eigenvalue blowup).
// X = R - eps*I; S = sign(X); R_psd = 0.5(X + X*S) + eps*I.
// 112^3 GEMMs, bf16 hi/lo 3-pass. One CTA (448 thr) per batch matrix.
// ---------------------------------------------------------------------------
#define NS_ITERS 38
#define NSD 112
#define NS_THREADS 448
#define NS_TRI (NSD * (NSD + 1) / 2)
#define O_S32 0                       // 112*112*4 = 50176
#define O_SHI 50176                   // 112*120*2 = 26880
#define O_SLO 77056
#define O_YHI 103936
#define O_YLO 130816
#define O_XHI 157696
#define O_XLO 184576
#define O_AUX 211456                  // 16 red + 112 inv floats
#define SMEM_NS (211456 + 512 + 64)

__device__ __forceinline__ void gemm_ab(uint32_t sb, uint32_t oAh, uint32_t oAl,
                                        uint32_t oBh, uint32_t oBl,
                                        int wm, int wn, int lane,
                                        float (&acc)[7][4]) {
#pragma unroll
  for (int nt = 0; nt < 7; nt++)
#pragma unroll
    for (int e = 0; e < 4; e++) acc[nt][e] = 0.f;
#pragma unroll
  for (int ks = 0; ks < 7; ks++) {
    uint32_t ah[4], al[4], bb[7][2];
    int arow = (lane & 7) + ((lane >> 3) & 1) * 8;
    uint32_t ra = (uint32_t)((wm * 16 + arow) * 240 + ks * 32 + ((lane >> 4) << 4));
    ldsm_x4(ah, sb + oAh + ra);
    ldsm_x4(al, sb + oAl + ra);
    int bl_ = lane & 15;
    int brow = bl_ & 7;
    int bco = ks * 32 + ((bl_ >> 3) << 4);
#pragma unroll
    for (int nt = 0; nt < 7; nt++) {
      uint32_t rb = (uint32_t)((wn * 56 + nt * 8 + brow) * 240 + bco);
      ldsm_x2(bb[nt], sb + oBh + rb);
    }
#pragma unroll
    for (int nt = 0; nt < 7; nt++) mma16816(acc[nt], ah, bb[nt]);
#pragma unroll
    for (int nt = 0; nt < 7; nt++) mma16816(acc[nt], al, bb[nt]);
#pragma unroll
    for (int nt = 0; nt < 7; nt++) {
      uint32_t rb = (uint32_t)((wn * 56 + nt * 8 + brow) * 240 + bco);
      ldsm_x2(bb[nt], sb + oBl + rb);
    }
#pragma unroll
    for (int nt = 0; nt < 7; nt++) mma16816(acc[nt], ah, bb[nt]);
  }
}

__global__ __launch_bounds__(NS_THREADS) void psd_kernel(float* __restrict__ out) {
  extern __shared__ char smem[];
  uint32_t sb = smem_u32(smem);
  float* S32 = (float*)(smem + O_S32);
  float* aux = (float*)(smem + O_AUX);
  int b = blockIdx.x;
  int tid = threadIdx.x, lane = tid & 31, warp = tid >> 5;
  int wm = warp % 7, wn = warp / 7;
  const float* Rg = g_R + (size_t)b * NA * NA;

  // ---- init: X = R - eps*I (padded to 112), Frobenius reduce ----
  float part = 0.f;
  for (int idx = tid; idx < NSD * NSD; idx += NS_THREADS) {
    int r = idx / NSD, c = idx - (idx / NSD) * NSD;
    float v = 0.f;
    if (r < NA && c < NA) v = (r == c) ? (1.0f - 1e-4f) : Rg[r * NA + c];
    S32[idx] = v;
    part += v * v;
  }
#pragma unroll
  for (int o = 16; o; o >>= 1) part += __shfl_xor_sync(0xffffffffu, part, o);
  if (lane == 0) aux[warp] = part;
  __syncthreads();
  if (tid == 0) {
    float s = 0.f;
    for (int w = 0; w < 14; w++) s += aux[w];
    float f = sqrtf(s);
    aux[14] = f;
    aux[15] = 1.0f / f;
  }
  __syncthreads();
  float fnorm = aux[14], invf = aux[15];

  // ---- normalize; split into S (iterate) and X (kept) bf16 hi/lo ----
  for (int idx = tid; idx < NSD * NSD; idx += NS_THREADS) {
    int r = idx / NSD, c = idx - (idx / NSD) * NSD;
    float v = S32[idx] * invf;
    S32[idx] = v;
    __nv_bfloat16 h = __float2bfloat16(v);
    __nv_bfloat16 l = __float2bfloat16(v - __bfloat162float(h));
    uint32_t off = (uint32_t)(r * 240 + c * 2);
    *(__nv_bfloat16*)(smem + O_SHI + off) = h;
    *(__nv_bfloat16*)(smem + O_SLO + off) = l;
    *(__nv_bfloat16*)(smem + O_XHI + off) = h;
    *(__nv_bfloat16*)(smem + O_XLO + off) = l;
  }
  __syncthreads();

  float acc[7][4];
  for (int it = 0; it < NS_ITERS; it++) {
    // Y = S * S^T (exactly symmetric in FP)
    gemm_ab(sb, O_SHI, O_SLO, O_SHI, O_SLO, wm, wn, lane, acc);
#pragma unroll
    for (int nt = 0; nt < 7; nt++) {
#pragma unroll
      for (int half = 0; half < 2; half++) {
        int row = wm * 16 + (lane >> 2) + half * 8;
        int col = wn * 56 + nt * 8 + 2 * (lane & 3);
        float a0 = acc[nt][half * 2 + 0], a1 = acc[nt][half * 2 + 1];
        __nv_bfloat16 h0 = __float2bfloat16(a0), h1 = __float2bfloat16(a1);
        float r0 = a0 - __bfloat162float(h0), r1 = a1 - __bfloat162float(h1);
        uint32_t hp = ((uint32_t)*(uint16_t*)&h1 << 16) | *(uint16_t*)&h0;
        uint32_t lp = pack_bf16(r0, r1);
        *(uint32_t*)(smem + O_YHI + row * 240 + col * 2) = hp;
        *(uint32_t*)(smem + O_YLO + row * 240 + col * 2) = lp;
      }
    }
    __syncthreads();
    // Z = S * Y ; S_new(fp32) = 1.5 S - 0.5 Z  (written to S32 only)
    gemm_ab(sb, O_SHI, O_SLO, O_YHI, O_YLO, wm, wn, lane, acc);
    __syncthreads();
#pragma unroll
    for (int nt = 0; nt < 7; nt++) {
#pragma unroll
      for (int half = 0; half < 2; half++) {
        int row = wm * 16 + (lane >> 2) + half * 8;
        int col = wn * 56 + nt * 8 + 2 * (lane & 3);
        int i0 = row * NSD + col;
        S32[i0]     = 1.5f * S32[i0]     - 0.5f * acc[nt][half * 2 + 0];
        S32[i0 + 1] = 1.5f * S32[i0 + 1] - 0.5f * acc[nt][half * 2 + 1];
      }
    }
    __syncthreads();
    // SYMMETRIZE: S <- (S + S^T)/2 (clamped), refresh bf16 hi/lo copies.
    // Each unordered pair {i,j} owned by one thread -> race-free.
    for (int idx = tid; idx < NS_TRI; idx += NS_THREADS) {
      int i = (int)((sqrtf(8.f * (float)idx + 1.f) - 1.f) * 0.5f);
      while (i * (i + 1) / 2 > idx) i--;
      while ((i + 1) * (i + 2) / 2 <= idx) i++;
      int j = idx - i * (i + 1) / 2;
      float avg = 0.5f * (S32[i * NSD + j] + S32[j * NSD + i]);
      avg = fminf(fmaxf(avg, -2.f), 2.f);
      S32[i * NSD + j] = avg;
      S32[j * NSD + i] = avg;
      __nv_bfloat16 h = __float2bfloat16(avg);
      __nv_bfloat16 l = __float2bfloat16(avg - __bfloat162float(h));
      uint32_t oij = (uint32_t)(i * 240 + j * 2);
      uint32_t oji = (uint32_t)(j * 240 + i * 2);
      *(__nv_bfloat16*)(smem + O_SHI + oij) = h;
      *(__nv_bfloat16*)(smem + O_SLO + oij) = l;
      *(__nv_bfloat16*)(smem + O_SHI + oji) = h;
      *(__nv_bfloat16*)(smem + O_SLO + oji) = l;
    }
    __syncthreads();
  }

  // ---- W = S * Xn ; P = 0.5(X + f*W) + eps*I (into S32) ----
  gemm_ab(sb, O_SHI, O_SLO, O_XHI, O_XLO, wm, wn, lane, acc);
  __syncthreads();
#pragma unroll
  for (int nt = 0; nt < 7; nt++) {
#pragma unroll
    for (int half = 0; half < 2; half++) {
      int row = wm * 16 + (lane >> 2) + half * 8;
      int col = wn * 56 + nt * 8 + 2 * (lane & 3);
#pragma unroll
      for (int j = 0; j < 2; j++) {
        int c = col + j;
        float Xg = 0.f;
        if (row < NA && c < NA)
          Xg = (row == c) ? (1.0f - 1e-4f) : Rg[row * NA + c];
        float P = 0.5f * (Xg + fnorm * acc[nt][half * 2 + j]) +
                  ((row == c) ? 1e-4f : 0.f);
        S32[row * NSD + c] = P;
      }
    }
  }
  __syncthreads();

  if (tid < NA) aux[16 + tid] = rsqrtf(fmaxf(S32[tid * (NSD + 1)], 1e-6f));
  __syncthreads();

  const float* vl = g_vols + b * NA;
  float* og = out + (size_t)b * NA * NA;
  for (int idx = tid; idx < NA * NA; idx += NS_THREADS) {
    int r = idx / NA, c = idx - (idx / NA) * NA;
    og[idx] = vl[r] * vl[c] * aux[16 + r] * aux[16 + c] * S32[r * NSD + c];
  }
}

// ---------------------------------------------------------------------------
extern "C" void kernel_launch(void* const* d_in, const int* in_sizes, int n_in,
                              void* d_out, int out_size) {
  const float* x   = (const float*)d_in[0];
  const float* vw1 = (const float*)d_in[1];
  const float* vb1 = (const float*)d_in[2];
  const float* vw2 = (const float*)d_in[3];
  const float* vb2 = (const float*)d_in[4];
  const float* cw1 = (const float*)d_in[5];
  const float* cb1 = (const float*)d_in[6];
  const float* cw2 = (const float*)d_in[7];
  const float* cb2 = (const float*)d_in[8];
  float* out = (float*)d_out;

  prep_w1t<<<HID, DM>>>(cw1);
  vols_kernel<<<dim3(7, BATCH), 256>>>(x, vw1, vb1, vw2, vb2);

  cudaFuncSetAttribute(pair_mma_kernel,
                       cudaFuncAttributeMaxDynamicSharedMemorySize, SMEM_PAIR);
  pair_mma_kernel<<<dim3(PTILES, BATCH), 256, SMEM_PAIR>>>(x, cb1, cw2, cb2);

  cudaFuncSetAttribute(psd_kernel,
                       cudaFuncAttributeMaxDynamicSharedMemorySize, SMEM_NS);
  psd_kernel<<<BATCH, NS_THREADS, SMEM_NS>>>(out);
}

// round 11
// speedup vs baseline: 3.0568x; 1.2092x over previous
#include <cuda_runtime.h>
#include <cuda_bf16.h>
#include <math.h>
#include <stdint.h>

#define NA 100
#define DM 256
#define HID 256
#define BATCH 64
#define NPAIR 4950
#define PT 64           // pairs per CTA tile
#define PTILES 78       // ceil(4950/64)

// ---------------- device scratch (no allocation allowed) ----------------
__device__ float g_R[BATCH * NA * NA];
__device__ float g_vols[BATCH * NA];
__device__ __nv_bfloat16 g_w1t_hi[HID * DM];  // [n][k] K-major
__device__ __nv_bfloat16 g_w1t_lo[HID * DM];

__device__ __forceinline__ uint32_t smem_u32(const void* p) {
  uint32_t a;
  asm("{ .reg .u64 t; cvta.to.shared.u64 t, %1; cvt.u32.u64 %0, t; }"
      : "=r"(a) : "l"(p));
  return a;
}
__device__ __forceinline__ void ldsm_x4(uint32_t (&r)[4], uint32_t addr) {
  asm volatile(
      "ldmatrix.sync.aligned.m8n8.x4.shared.b16 {%0,%1,%2,%3}, [%4];"
      : "=r"(r[0]), "=r"(r[1]), "=r"(r[2]), "=r"(r[3]) : "r"(addr));
}
__device__ __forceinline__ void ldsm_x2(uint32_t (&r)[2], uint32_t addr) {
  asm volatile(
      "ldmatrix.sync.aligned.m8n8.x2.shared.b16 {%0,%1}, [%2];"
      : "=r"(r[0]), "=r"(r[1]) : "r"(addr));
}
__device__ __forceinline__ void mma16816(float (&d)[4], const uint32_t (&a)[4],
                                         const uint32_t (&b)[2]) {
  asm volatile(
      "mma.sync.aligned.m16n8k16.row.col.f32.bf16.bf16.f32 "
      "{%0,%1,%2,%3}, {%4,%5,%6,%7}, {%8,%9}, {%0,%1,%2,%3};"
      : "+f"(d[0]), "+f"(d[1]), "+f"(d[2]), "+f"(d[3])
      : "r"(a[0]), "r"(a[1]), "r"(a[2]), "r"(a[3]), "r"(b[0]), "r"(b[1]));
}
__device__ __forceinline__ uint32_t pack_bf16(float a, float b) {
  __nv_bfloat16 h0 = __float2bfloat16(a), h1 = __float2bfloat16(b);
  return ((uint32_t)*(uint16_t*)&h1 << 16) | *(uint16_t*)&h0;
}

// ---------------------------------------------------------------------------
__global__ void prep_w1t(const float* __restrict__ w1) {
  int n = blockIdx.x, k = threadIdx.x;
  float v = w1[k * HID + n];
  __nv_bfloat16 h = __float2bfloat16(v);
  float r = v - __bfloat162float(h);
  g_w1t_hi[n * DM + k] = h;
  g_w1t_lo[n * DM + k] = __float2bfloat16(r);
}

// ---------------------------------------------------------------------------
__global__ __launch_bounds__(256) void vols_kernel(
    const float* __restrict__ x, const float* __restrict__ w1,
    const float* __restrict__ b1, const float* __restrict__ w2,
    const float* __restrict__ b2) {
  int b = blockIdx.y;
  int r0 = blockIdx.x * 16;
  const float* emb = x + ((size_t)b * 64 + 63) * NA * DM;
  __shared__ float es[16][DM];
  __shared__ float red[16][8];
  int tid = threadIdx.x;
  int lane = tid & 31, warp = tid >> 5;

  for (int idx = tid; idx < 16 * DM; idx += 256) {
    int r = idx >> 8, d = idx & 255;
    es[r][d] = (r0 + r < NA) ? emb[(r0 + r) * DM + d] : 0.f;
  }
  __syncthreads();

  float acc[16];
  float bb = b1[tid];
#pragma unroll
  for (int r = 0; r < 16; r++) acc[r] = bb;

#pragma unroll 4
  for (int d = 0; d < DM; d++) {
    float w = w1[d * HID + tid];
#pragma unroll
    for (int r = 0; r < 16; r++) acc[r] = fmaf(es[r][d], w, acc[r]);
  }

  float wv = w2[tid];
#pragma unroll
  for (int r = 0; r < 16; r++) {
    float v = fmaxf(acc[r], 0.f) * wv;
#pragma unroll
    for (int o = 16; o; o >>= 1) v += __shfl_xor_sync(0xffffffffu, v, o);
    if (lane == 0) red[r][warp] = v;
  }
  __syncthreads();
  if (tid < 16) {
    float s = 0.f;
#pragma unroll
    for (int w = 0; w < 8; w++) s += red[tid][w];
    s += b2[0];
    float sp = fmaxf(s, 0.f) + log1pf(expf(-fabsf(s)));
    if (r0 + tid < NA) g_vols[b * NA + r0 + tid] = sp + 1e-6f;
  }
}

// ---------------------------------------------------------------------------
// pair MLP via mma.sync bf16 (2-way split, 3 passes), 256 threads,
// warp tile 32x64, register prefetch of next K-chunk. (measured 540us)
// ---------------------------------------------------------------------------
#define OFF_A_HI 0
#define OFF_A_LO 5120
#define OFF_B_HI 10240
#define OFF_B_LO 30720
#define OFF_SI   51200
#define OFF_SJ   51456
#define OFF_B1   51712
#define OFF_W2   52736
#define OFF_RED  53760
#define SMEM_PAIR 54784

__global__ __launch_bounds__(256) void pair_mma_kernel(
    const float* __restrict__ x, const float* __restrict__ b1,
    const float* __restrict__ w2, const float* __restrict__ b2) {
  extern __shared__ char smem[];
  uint32_t sb = smem_u32(smem);
  int b = blockIdx.y, tile = blockIdx.x;
  int tid = threadIdx.x, lane = tid & 31, warp = tid >> 5;
  int wm = warp >> 2, wn = warp & 3;   // 2 x 4 warps
  const float* emb = x + ((size_t)b * 64 + 63) * NA * DM;

  int* si = (int*)(smem + OFF_SI);
  int* sj = (int*)(smem + OFF_SJ);
  float* b1s = (float*)(smem + OFF_B1);
  float* w2s = (float*)(smem + OFF_W2);
  float* red = (float*)(smem + OFF_RED);

  if (tid < PT) {
    int k = tile * PT + tid;
    if (k >= NPAIR) k = NPAIR - 1;
    int i = (int)((1.0f + sqrtf(1.0f + 8.0f * (float)k)) * 0.5f);
    while ((i * (i - 1)) / 2 > k) i--;
    while (((i + 1) * i) / 2 <= k) i++;
    si[tid] = i;
    sj[tid] = k - (i * (i - 1)) / 2;
  }
  b1s[tid] = b1[tid];
  w2s[tid] = w2[tid];
  __syncthreads();

  float acc[2][8][4];
#pragma unroll
  for (int mt = 0; mt < 2; mt++)
#pragma unroll
    for (int nt = 0; nt < 8; nt++)
#pragma unroll
      for (int e = 0; e < 4; e++) acc[mt][nt][e] = 0.f;

  float2 Aea[4], Aeb[4];
  uint4 Bh[4], Bl[4];

#pragma unroll
  for (int t = 0; t < 4; t++) {
    int idx = tid + t * 256;
    int row = idx >> 4, kk2 = idx & 15;
    Aea[t] = *(const float2*)(emb + si[row] * DM + 2 * kk2);
    Aeb[t] = *(const float2*)(emb + sj[row] * DM + 2 * kk2);
  }
#pragma unroll
  for (int t = 0; t < 4; t++) {
    int idx = tid + t * 256;
    int n = idx >> 2, kg = idx & 3;
    Bh[t] = *(const uint4*)(g_w1t_hi + n * DM + kg * 8);
    Bl[t] = *(const uint4*)(g_w1t_lo + n * DM + kg * 8);
  }

  for (int ch = 0; ch < 8; ch++) {
#pragma unroll
    for (int t = 0; t < 4; t++) {
      int idx = tid + t * 256;
      int row = idx >> 4, kk2 = idx & 15;
      float p0 = Aea[t].x * Aeb[t].x, p1 = Aea[t].y * Aeb[t].y;
      __nv_bfloat16 h0 = __float2bfloat16(p0);
      __nv_bfloat16 h1 = __float2bfloat16(p1);
      __nv_bfloat16 l0 = __float2bfloat16(p0 - __bfloat162float(h0));
      __nv_bfloat16 l1 = __float2bfloat16(p1 - __bfloat162float(h1));
      uint32_t hp = ((uint32_t)*(uint16_t*)&h1 << 16) | *(uint16_t*)&h0;
      uint32_t lp = ((uint32_t)*(uint16_t*)&l1 << 16) | *(uint16_t*)&l0;
      *(uint32_t*)(smem + OFF_A_HI + row * 80 + kk2 * 4) = hp;
      *(uint32_t*)(smem + OFF_A_LO + row * 80 + kk2 * 4) = lp;
    }
#pragma unroll
    for (int t = 0; t < 4; t++) {
      int idx = tid + t * 256;
      int n = idx >> 2, kg = idx & 3;
      *(uint4*)(smem + OFF_B_HI + n * 80 + kg * 16) = Bh[t];
      *(uint4*)(smem + OFF_B_LO + n * 80 + kg * 16) = Bl[t];
    }
    __syncthreads();

    if (ch < 7) {
      int k0 = (ch + 1) * 32;
#pragma unroll
      for (int t = 0; t < 4; t++) {
        int idx = tid + t * 256;
        int row = idx >> 4, kk2 = idx & 15;
        Aea[t] = *(const float2*)(emb + si[row] * DM + k0 + 2 * kk2);
        Aeb[t] = *(const float2*)(emb + sj[row] * DM + k0 + 2 * kk2);
      }
#pragma unroll
      for (int t = 0; t < 4; t++) {
        int idx = tid + t * 256;
        int n = idx >> 2, kg = idx & 3;
        Bh[t] = *(const uint4*)(g_w1t_hi + n * DM + k0 + kg * 8);
        Bl[t] = *(const uint4*)(g_w1t_lo + n * DM + k0 + kg * 8);
      }
    }

#pragma unroll
    for (int ks = 0; ks < 2; ks++) {
      uint32_t ah[2][4], al[2][4], bb[8][2];
      int arow = (lane & 7) + ((lane >> 3) & 1) * 8;
      int acolb = ks * 32 + ((lane >> 4) << 4);
#pragma unroll
      for (int mt = 0; mt < 2; mt++) {
        uint32_t ra = (uint32_t)((wm * 32 + mt * 16 + arow) * 80 + acolb);
        ldsm_x4(ah[mt], sb + OFF_A_HI + ra);
        ldsm_x4(al[mt], sb + OFF_A_LO + ra);
      }
      int bl_ = lane & 15;
      int brow = bl_ & 7;
      int bcolb = ks * 32 + ((bl_ >> 3) << 4);
#pragma unroll
      for (int nt = 0; nt < 8; nt++) {
        uint32_t rb = (uint32_t)((wn * 64 + nt * 8 + brow) * 80 + bcolb);
        ldsm_x2(bb[nt], sb + OFF_B_HI + rb);
      }
#pragma unroll
      for (int mt = 0; mt < 2; mt++)
#pragma unroll
        for (int nt = 0; nt < 8; nt++) mma16816(acc[mt][nt], ah[mt], bb[nt]);
#pragma unroll
      for (int mt = 0; mt < 2; mt++)
#pragma unroll
        for (int nt = 0; nt < 8; nt++) mma16816(acc[mt][nt], al[mt], bb[nt]);
#pragma unroll
      for (int nt = 0; nt < 8; nt++) {
        uint32_t rb = (uint32_t)((wn * 64 + nt * 8 + brow) * 80 + bcolb);
        ldsm_x2(bb[nt], sb + OFF_B_LO + rb);
      }
#pragma unroll
      for (int mt = 0; mt < 2; mt++)
#pragma unroll
        for (int nt = 0; nt < 8; nt++) mma16816(acc[mt][nt], ah[mt], bb[nt]);
    }
    __syncthreads();
  }

#pragma unroll
  for (int mt = 0; mt < 2; mt++) {
#pragma unroll
    for (int half = 0; half < 2; half++) {
      float s = 0.f;
#pragma unroll
      for (int nt = 0; nt < 8; nt++) {
        int col = wn * 64 + nt * 8 + 2 * (lane & 3);
        float h0 = acc[mt][nt][half * 2 + 0] + b1s[col];
        float h1 = acc[mt][nt][half * 2 + 1] + b1s[col + 1];
        s = fmaf(fmaxf(h0, 0.f), w2s[col], s);
        s = fmaf(fmaxf(h1, 0.f), w2s[col + 1], s);
      }
      s += __shfl_xor_sync(0xffffffffu, s, 1);
      s += __shfl_xor_sync(0xffffffffu, s, 2);
      if ((lane & 3) == 0) {
        int row = wm * 32 + mt * 16 + half * 8 + (lane >> 2);
        red[row * 4 + wn] = s;
      }
    }
  }
  __syncthreads();
  if (tid < PT) {
    int k = tile * PT + tid;
    if (k < NPAIR) {
      float s = red[tid * 4] + red[tid * 4 + 1] + red[tid * 4 + 2] +
                red[tid * 4 + 3] + b2[0];
      float t = tanhf(s);
      int i = si[tid], j = sj[tid];
      g_R[(size_t)b * NA * NA + i * NA + j] = t;
      g_R[(size_t)b * NA * NA + j * NA + i] = t;
    }
  }
}

// ---------------------------------------------------------------------------
// PSD projection via HYBRID matrix-sign iteration (no eigensolver):
//   Phase 1 (13 iters, quintic): S <- aS + bS^3 + cS^5, (a,b,c) Muon-style,
//            lifts tiny eigenvalues 3.44x/iter into band [0.68, 1.21].
//   Phase 2 (5 iters, cubic): S <- 1.5S - 0.5S^3, quadratic polish to ~1e-9.
//   Per-iteration explicit symmetrization (stability guarantee).
//   R_psd = 0.5(X + X*S) + eps*I.  112^3 GEMMs, bf16 hi/lo 3-pass.
// One CTA (448 thr) per batch matrix.
// ---------------------------------------------------------------------------
#define QI 13
#define CI 5
#define QA 3.4445f
#define QB (-4.7750f)
#define QC 2.0315f
#define NSD 112
#define NS_THREADS 448
#define NS_TRI (NSD * (NSD + 1) / 2)
#define O_S32 0                       // 112*112*4 = 50176
#define O_SHI 50176                   // 112*120*2 = 26880 each
#define O_SLO 77056
#define O_YHI 103936
#define O_YLO 130816
#define O_THI 157696                  // T scratch (was X; X rebuilt at end)
#define O_TLO 184576
#define O_AUX 211456
#define SMEM_NS (211456 + 512 + 64)

__device__ __forceinline__ void gemm_ab(uint32_t sb, uint32_t oAh, uint32_t oAl,
                                        uint32_t oBh, uint32_t oBl,
                                        int wm, int wn, int lane,
                                        float (&acc)[7][4]) {
#pragma unroll
  for (int nt = 0; nt < 7; nt++)
#pragma unroll
    for (int e = 0; e < 4; e++) acc[nt][e] = 0.f;
#pragma unroll
  for (int ks = 0; ks < 7; ks++) {
    uint32_t ah[4], al[4], bb[7][2];
    int arow = (lane & 7) + ((lane >> 3) & 1) * 8;
    uint32_t ra = (uint32_t)((wm * 16 + arow) * 240 + ks * 32 + ((lane >> 4) << 4));
    ldsm_x4(ah, sb + oAh + ra);
    ldsm_x4(al, sb + oAl + ra);
    int bl_ = lane & 15;
    int brow = bl_ & 7;
    int bco = ks * 32 + ((bl_ >> 3) << 4);
#pragma unroll
    for (int nt = 0; nt < 7; nt++) {
      uint32_t rb = (uint32_t)((wn * 56 + nt * 8 + brow) * 240 + bco);
      ldsm_x2(bb[nt], sb + oBh + rb);
    }
#pragma unroll
    for (int nt = 0; nt < 7; nt++) mma16816(acc[nt], ah, bb[nt]);
#pragma unroll
    for (int nt = 0; nt < 7; nt++) mma16816(acc[nt], al, bb[nt]);
#pragma unroll
    for (int nt = 0; nt < 7; nt++) {
      uint32_t rb = (uint32_t)((wn * 56 + nt * 8 + brow) * 240 + bco);
      ldsm_x2(bb[nt], sb + oBl + rb);
    }
#pragma unroll
    for (int nt = 0; nt < 7; nt++) mma16816(acc[nt], ah, bb[nt]);
  }
}

__global__ __launch_bounds__(NS_THREADS) void psd_kernel(float* __restrict__ out) {
  extern __shared__ char smem[];
  uint32_t sb = smem_u32(smem);
  float* S32 = (float*)(smem + O_S32);
  float* aux = (float*)(smem + O_AUX);
  int b = blockIdx.x;
  int tid = threadIdx.x, lane = tid & 31, warp = tid >> 5;
  int wm = warp % 7, wn = warp / 7;
  const float* Rg = g_R + (size_t)b * NA * NA;

  // ---- init: X = R - eps*I (padded to 112), Frobenius reduce ----
  float part = 0.f;
  for (int idx = tid; idx < NSD * NSD; idx += NS_THREADS) {
    int r = idx / NSD, c = idx - (idx / NSD) * NSD;
    float v = 0.f;
    if (r < NA && c < NA) v = (r == c) ? (1.0f - 1e-4f) : Rg[r * NA + c];
    S32[idx] = v;
    part += v * v;
  }
#pragma unroll
  for (int o = 16; o; o >>= 1) part += __shfl_xor_sync(0xffffffffu, part, o);
  if (lane == 0) aux[warp] = part;
  __syncthreads();
  if (tid == 0) {
    float s = 0.f;
    for (int w = 0; w < 14; w++) s += aux[w];
    float f = sqrtf(s);
    aux[14] = f;
    aux[15] = 1.0f / f;
  }
  __syncthreads();
  float fnorm = aux[14], invf = aux[15];

  // ---- normalize; S (fp32 + bf16 hi/lo) ----
  for (int idx = tid; idx < NSD * NSD; idx += NS_THREADS) {
    int r = idx / NSD, c = idx - (idx / NSD) * NSD;
    float v = S32[idx] * invf;
    S32[idx] = v;
    __nv_bfloat16 h = __float2bfloat16(v);
    __nv_bfloat16 l = __float2bfloat16(v - __bfloat162float(h));
    uint32_t off = (uint32_t)(r * 240 + c * 2);
    *(__nv_bfloat16*)(smem + O_SHI + off) = h;
    *(__nv_bfloat16*)(smem + O_SLO + off) = l;
  }
  __syncthreads();

  float acc[7][4];

  // ================= Phase 1: quintic (3 GEMMs/iter) =================
  for (int it = 0; it < QI; it++) {
    // Y = S*S (exactly symmetric)
    gemm_ab(sb, O_SHI, O_SLO, O_SHI, O_SLO, wm, wn, lane, acc);
#pragma unroll
    for (int nt = 0; nt < 7; nt++) {
#pragma unroll
      for (int half = 0; half < 2; half++) {
        int row = wm * 16 + (lane >> 2) + half * 8;
        int col = wn * 56 + nt * 8 + 2 * (lane & 3);
        float a0 = acc[nt][half * 2 + 0], a1 = acc[nt][half * 2 + 1];
        __nv_bfloat16 h0 = __float2bfloat16(a0), h1 = __float2bfloat16(a1);
        float r0 = a0 - __bfloat162float(h0), r1 = a1 - __bfloat162float(h1);
        uint32_t hp = ((uint32_t)*(uint16_t*)&h1 << 16) | *(uint16_t*)&h0;
        uint32_t lp = pack_bf16(r0, r1);
        *(uint32_t*)(smem + O_YHI + row * 240 + col * 2) = hp;
        *(uint32_t*)(smem + O_YLO + row * 240 + col * 2) = lp;
      }
    }
    __syncthreads();
    // Z = Y*Y ; T = QA*I + QB*Y + QC*Z  (bf16 hi/lo into T buffers)
    gemm_ab(sb, O_YHI, O_YLO, O_YHI, O_YLO, wm, wn, lane, acc);
    __syncthreads();
#pragma unroll
    for (int nt = 0; nt < 7; nt++) {
#pragma unroll
      for (int half = 0; half < 2; half++) {
        int row = wm * 16 + (lane >> 2) + half * 8;
        int col = wn * 56 + nt * 8 + 2 * (lane & 3);
        float t01[2];
#pragma unroll
        for (int j = 0; j < 2; j++) {
          int c = col + j;
          uint32_t off = (uint32_t)(row * 240 + c * 2);
          float y = __bfloat162float(*(__nv_bfloat16*)(smem + O_YHI + off)) +
                    __bfloat162float(*(__nv_bfloat16*)(smem + O_YLO + off));
          t01[j] = ((row == c) ? QA : 0.f) + QB * y + QC * acc[nt][half * 2 + j];
        }
        __nv_bfloat16 h0 = __float2bfloat16(t01[0]), h1 = __float2bfloat16(t01[1]);
        float r0 = t01[0] - __bfloat162float(h0), r1 = t01[1] - __bfloat162float(h1);
        uint32_t hp = ((uint32_t)*(uint16_t*)&h1 << 16) | *(uint16_t*)&h0;
        uint32_t lp = pack_bf16(r0, r1);
        *(uint32_t*)(smem + O_THI + row * 240 + col * 2) = hp;
        *(uint32_t*)(smem + O_TLO + row * 240 + col * 2) = lp;
      }
    }
    __syncthreads();
    // S' = S*T (S,T commute in exact arithmetic -> near-symmetric)
    gemm_ab(sb, O_SHI, O_SLO, O_THI, O_TLO, wm, wn, lane, acc);
    __syncthreads();
#pragma unroll
    for (int nt = 0; nt < 7; nt++) {
#pragma unroll
      for (int half = 0; half < 2; half++) {
        int row = wm * 16 + (lane >> 2) + half * 8;
        int col = wn * 56 + nt * 8 + 2 * (lane & 3);
        int i0 = row * NSD + col;
        S32[i0]     = acc[nt][half * 2 + 0];
        S32[i0 + 1] = acc[nt][half * 2 + 1];
      }
    }
    __syncthreads();
    // SYMMETRIZE + clamp + refresh bf16 S
    for (int idx = tid; idx < NS_TRI; idx += NS_THREADS) {
      int i = (int)((sqrtf(8.f * (float)idx + 1.f) - 1.f) * 0.5f);
      while (i * (i + 1) / 2 > idx) i--;
      while ((i + 1) * (i + 2) / 2 <= idx) i++;
      int j = idx - i * (i + 1) / 2;
      float avg = 0.5f * (S32[i * NSD + j] + S32[j * NSD + i]);
      avg = fminf(fmaxf(avg, -2.f), 2.f);
      S32[i * NSD + j] = avg;
      S32[j * NSD + i] = avg;
      __nv_bfloat16 h = __float2bfloat16(avg);
      __nv_bfloat16 l = __float2bfloat16(avg - __bfloat162float(h));
      uint32_t oij = (uint32_t)(i * 240 + j * 2);
      uint32_t oji = (uint32_t)(j * 240 + i * 2);
      *(__nv_bfloat16*)(smem + O_SHI + oij) = h;
      *(__nv_bfloat16*)(smem + O_SLO + oij) = l;
      *(__nv_bfloat16*)(smem + O_SHI + oji) = h;
      *(__nv_bfloat16*)(smem + O_SLO + oji) = l;
    }
    __syncthreads();
  }

  // ================= Phase 2: cubic polish (2 GEMMs/iter) =================
  for (int it = 0; it < CI; it++) {
    gemm_ab(sb, O_SHI, O_SLO, O_SHI, O_SLO, wm, wn, lane, acc);
#pragma unroll
    for (int nt = 0; nt < 7; nt++) {
#pragma unroll
      for (int half = 0; half < 2; half++) {
        int row = wm * 16 + (lane >> 2) + half * 8;
        int col = wn * 56 + nt * 8 + 2 * (lane & 3);
        float a0 = acc[nt][half * 2 + 0], a1 = acc[nt][half * 2 + 1];
        __nv_bfloat16 h0 = __float2bfloat16(a0), h1 = __float2bfloat16(a1);
        float r0 = a0 - __bfloat162float(h0), r1 = a1 - __bfloat162float(h1);
        uint32_t hp = ((uint32_t)*(uint16_t*)&h1 << 16) | *(uint16_t*)&h0;
        uint32_t lp = pack_bf16(r0, r1);
        *(uint32_t*)(smem + O_YHI + row * 240 + col * 2) = hp;
        *(uint32_t*)(smem + O_YLO + row * 240 + col * 2) = lp;
      }
    }
    __syncthreads();
    gemm_ab(sb, O_SHI, O_SLO, O_YHI, O_YLO, wm, wn, lane, acc);
    __syncthreads();
#pragma unroll
    for (int nt = 0; nt < 7; nt++) {
#pragma unroll
      for (int half = 0; half < 2; half++) {
        int row = wm * 16 + (lane >> 2) + half * 8;
        int col = wn * 56 + nt * 8 + 2 * (lane & 3);
        int i0 = row * NSD + col;
        S32[i0]     = 1.5f * S32[i0]     - 0.5f * acc[nt][half * 2 + 0];
        S32[i0 + 1] = 1.5f * S32[i0 + 1] - 0.5f * acc[nt][half * 2 + 1];
      }
    }
    __syncthreads();
    for (int idx = tid; idx < NS_TRI; idx += NS_THREADS) {
      int i = (int)((sqrtf(8.f * (float)idx + 1.f) - 1.f) * 0.5f);
      while (i * (i + 1) / 2 > idx) i--;
      while ((i + 1) * (i + 2) / 2 <= idx) i++;
      int j = idx - i * (i + 1) / 2;
      float avg = 0.5f * (S32[i * NSD + j] + S32[j * NSD + i]);
      avg = fminf(fmaxf(avg, -2.f), 2.f);
      S32[i * NSD + j] = avg;
      S32[j * NSD + i] = avg;
      __nv_bfloat16 h = __float2bfloat16(avg);
      __nv_bfloat16 l = __float2bfloat16(avg - __bfloat162float(h));
      uint32_t oij = (uint32_t)(i * 240 + j * 2);
      uint32_t oji = (uint32_t)(j * 240 + i * 2);
      *(__nv_bfloat16*)(smem + O_SHI + oij) = h;
      *(__nv_bfloat16*)(smem + O_SLO + oij) = l;
      *(__nv_bfloat16*)(smem + O_SHI + oji) = h;
      *(__nv_bfloat16*)(smem + O_SLO + oji) = l;
    }
    __syncthreads();
  }

  // ---- rebuild Xn bf16 into Y buffers, W = S*Xn ; P = 0.5(X+f*W)+eps*I ----
  for (int idx = tid; idx < NSD * NSD; idx += NS_THREADS) {
    int r = idx / NSD, c = idx - (idx / NSD) * NSD;
    float v = 0.f;
    if (r < NA && c < NA)
      v = ((r == c) ? (1.0f - 1e-4f) : Rg[r * NA + c]) * invf;
    __nv_bfloat16 h = __float2bfloat16(v);
    __nv_bfloat16 l = __float2bfloat16(v - __bfloat162float(h));
    uint32_t off = (uint32_t)(r * 240 + c * 2);
    *(__nv_bfloat16*)(smem + O_YHI + off) = h;
    *(__nv_bfloat16*)(smem + O_YLO + off) = l;
  }
  __syncthreads();
  gemm_ab(sb, O_SHI, O_SLO, O_YHI, O_YLO, wm, wn, lane, acc);
  __syncthreads();
#pragma unroll
  for (int nt = 0; nt < 7; nt++) {
#pragma unroll
    for (int half = 0; half < 2; half++) {
      int row = wm * 16 + (lane >> 2) + half * 8;
      int col = wn * 56 + nt * 8 + 2 * (lane & 3);
#pragma unroll
      for (int j = 0; j < 2; j++) {
        int c = col + j;
        float Xg = 0.f;
        if (row < NA && c < NA)
          Xg = (row == c) ? (1.0f - 1e-4f) : Rg[row * NA + c];
        float P = 0.5f * (Xg + fnorm * acc[nt][half * 2 + j]) +
                  ((row == c) ? 1e-4f : 0.f);
        S32[row * NSD + c] = P;
      }
    }
  }
  __syncthreads();

  if (tid < NA) aux[16 + tid] = rsqrtf(fmaxf(S32[tid * (NSD + 1)], 1e-6f));
  __syncthreads();

  const float* vl = g_vols + b * NA;
  float* og = out + (size_t)b * NA * NA;
  for (int idx = tid; idx < NA * NA; idx += NS_THREADS) {
    int r = idx / NA, c = idx - (idx / NA) * NA;
    og[idx] = vl[r] * vl[c] * aux[16 + r] * aux[16 + c] * S32[r * NSD + c];
  }
}

// ---------------------------------------------------------------------------
extern "C" void kernel_launch(void* const* d_in, const int* in_sizes, int n_in,
                              void* d_out, int out_size) {
  const float* x   = (const float*)d_in[0];
  const float* vw1 = (const float*)d_in[1];
  const float* vb1 = (const float*)d_in[2];
  const float* vw2 = (const float*)d_in[3];
  const float* vb2 = (const float*)d_in[4];
  const float* cw1 = (const float*)d_in[5];
  const float* cb1 = (const float*)d_in[6];
  const float* cw2 = (const float*)d_in[7];
  const float* cb2 = (const float*)d_in[8];
  float* out = (float*)d_out;

  prep_w1t<<<HID, DM>>>(cw1);
  vols_kernel<<<dim3(7, BATCH), 256>>>(x, vw1, vb1, vw2, vb2);

  cudaFuncSetAttribute(pair_mma_kernel,
                       cudaFuncAttributeMaxDynamicSharedMemorySize, SMEM_PAIR);
  pair_mma_kernel<<<dim3(PTILES, BATCH), 256, SMEM_PAIR>>>(x, cb1, cw2, cb2);

  cudaFuncSetAttribute(psd_kernel,
                       cudaFuncAttributeMaxDynamicSharedMemorySize, SMEM_NS);
  psd_kernel<<<BATCH, NS_THREADS, SMEM_NS>>>(out);
}

// round 12
// speedup vs baseline: 3.3566x; 1.0981x over previous
#include <cuda_runtime.h>
#include <cuda_bf16.h>
#include <math.h>
#include <stdint.h>

#define NA 100
#define DM 256
#define HID 256
#define BATCH 64
#define NPAIR 4950
#define PT 64           // pairs per CTA tile
#define PTILES 78       // ceil(4950/64)

// ---------------- device scratch (no allocation allowed) ----------------
__device__ float g_R[BATCH * NA * NA];
__device__ float g_vols[BATCH * NA];
__device__ __nv_bfloat16 g_w1t_hi[HID * DM];  // [n][k] K-major
__device__ __nv_bfloat16 g_w1t_lo[HID * DM];

__device__ __forceinline__ uint32_t smem_u32(const void* p) {
  uint32_t a;
  asm("{ .reg .u64 t; cvta.to.shared.u64 t, %1; cvt.u32.u64 %0, t; }"
      : "=r"(a) : "l"(p));
  return a;
}
__device__ __forceinline__ void ldsm_x4(uint32_t (&r)[4], uint32_t addr) {
  asm volatile(
      "ldmatrix.sync.aligned.m8n8.x4.shared.b16 {%0,%1,%2,%3}, [%4];"
      : "=r"(r[0]), "=r"(r[1]), "=r"(r[2]), "=r"(r[3]) : "r"(addr));
}
__device__ __forceinline__ void ldsm_x2(uint32_t (&r)[2], uint32_t addr) {
  asm volatile(
      "ldmatrix.sync.aligned.m8n8.x2.shared.b16 {%0,%1}, [%2];"
      : "=r"(r[0]), "=r"(r[1]) : "r"(addr));
}
__device__ __forceinline__ void mma16816(float (&d)[4], const uint32_t (&a)[4],
                                         const uint32_t (&b)[2]) {
  asm volatile(
      "mma.sync.aligned.m16n8k16.row.col.f32.bf16.bf16.f32 "
      "{%0,%1,%2,%3}, {%4,%5,%6,%7}, {%8,%9}, {%0,%1,%2,%3};"
      : "+f"(d[0]), "+f"(d[1]), "+f"(d[2]), "+f"(d[3])
      : "r"(a[0]), "r"(a[1]), "r"(a[2]), "r"(a[3]), "r"(b[0]), "r"(b[1]));
}
__device__ __forceinline__ uint32_t pack_bf16(float a, float b) {
  __nv_bfloat16 h0 = __float2bfloat16(a), h1 = __float2bfloat16(b);
  return ((uint32_t)*(uint16_t*)&h1 << 16) | *(uint16_t*)&h0;
}

// ---------------------------------------------------------------------------
__global__ void prep_w1t(const float* __restrict__ w1) {
  int n = blockIdx.x, k = threadIdx.x;
  float v = w1[k * HID + n];
  __nv_bfloat16 h = __float2bfloat16(v);
  float r = v - __bfloat162float(h);
  g_w1t_hi[n * DM + k] = h;
  g_w1t_lo[n * DM + k] = __float2bfloat16(r);
}

// ---------------------------------------------------------------------------
__global__ __launch_bounds__(256) void vols_kernel(
    const float* __restrict__ x, const float* __restrict__ w1,
    const float* __restrict__ b1, const float* __restrict__ w2,
    const float* __restrict__ b2) {
  int b = blockIdx.y;
  int r0 = blockIdx.x * 16;
  const float* emb = x + ((size_t)b * 64 + 63) * NA * DM;
  __shared__ float es[16][DM];
  __shared__ float red[16][8];
  int tid = threadIdx.x;
  int lane = tid & 31, warp = tid >> 5;

  for (int idx = tid; idx < 16 * DM; idx += 256) {
    int r = idx >> 8, d = idx & 255;
    es[r][d] = (r0 + r < NA) ? emb[(r0 + r) * DM + d] : 0.f;
  }
  __syncthreads();

  float acc[16];
  float bb = b1[tid];
#pragma unroll
  for (int r = 0; r < 16; r++) acc[r] = bb;

#pragma unroll 4
  for (int d = 0; d < DM; d++) {
    float w = w1[d * HID + tid];
#pragma unroll
    for (int r = 0; r < 16; r++) acc[r] = fmaf(es[r][d], w, acc[r]);
  }

  float wv = w2[tid];
#pragma unroll
  for (int r = 0; r < 16; r++) {
    float v = fmaxf(acc[r], 0.f) * wv;
#pragma unroll
    for (int o = 16; o; o >>= 1) v += __shfl_xor_sync(0xffffffffu, v, o);
    if (lane == 0) red[r][warp] = v;
  }
  __syncthreads();
  if (tid < 16) {
    float s = 0.f;
#pragma unroll
    for (int w = 0; w < 8; w++) s += red[tid][w];
    s += b2[0];
    float sp = fmaxf(s, 0.f) + log1pf(expf(-fabsf(s)));
    if (r0 + tid < NA) g_vols[b * NA + r0 + tid] = sp + 1e-6f;
  }
}

// ---------------------------------------------------------------------------
// pair MLP via mma.sync bf16 (2-way split, 3 passes), 256 threads,
// warp tile 32x64. __launch_bounds__(256,2) -> <=128 regs -> 2 CTAs/SM so
// one CTA's MMA overlaps the other's staging. No register prefetch.
// ---------------------------------------------------------------------------
#define OFF_A_HI 0
#define OFF_A_LO 5120
#define OFF_B_HI 10240
#define OFF_B_LO 30720
#define OFF_SI   51200
#define OFF_SJ   51456
#define OFF_B1   51712
#define OFF_W2   52736
#define OFF_RED  53760
#define SMEM_PAIR 54784

__global__ __launch_bounds__(256, 2) void pair_mma_kernel(
    const float* __restrict__ x, const float* __restrict__ b1,
    const float* __restrict__ w2, const float* __restrict__ b2) {
  extern __shared__ char smem[];
  uint32_t sb = smem_u32(smem);
  int b = blockIdx.y, tile = blockIdx.x;
  int tid = threadIdx.x, lane = tid & 31, warp = tid >> 5;
  int wm = warp >> 2, wn = warp & 3;   // 2 x 4 warps
  const float* emb = x + ((size_t)b * 64 + 63) * NA * DM;

  int* si = (int*)(smem + OFF_SI);
  int* sj = (int*)(smem + OFF_SJ);
  float* b1s = (float*)(smem + OFF_B1);
  float* w2s = (float*)(smem + OFF_W2);
  float* red = (float*)(smem + OFF_RED);

  if (tid < PT) {
    int k = tile * PT + tid;
    if (k >= NPAIR) k = NPAIR - 1;
    int i = (int)((1.0f + sqrtf(1.0f + 8.0f * (float)k)) * 0.5f);
    while ((i * (i - 1)) / 2 > k) i--;
    while (((i + 1) * i) / 2 <= k) i++;
    si[tid] = i;
    sj[tid] = k - (i * (i - 1)) / 2;
  }
  b1s[tid] = b1[tid];
  w2s[tid] = w2[tid];
  __syncthreads();

  float acc[2][8][4];
#pragma unroll
  for (int mt = 0; mt < 2; mt++)
#pragma unroll
    for (int nt = 0; nt < 8; nt++)
#pragma unroll
      for (int e = 0; e < 4; e++) acc[mt][nt][e] = 0.f;

  for (int ch = 0; ch < 8; ch++) {
    int k0 = ch * 32;
    // A: 64x32 pair products, hi/lo split (1024 float2 -> 4 iters)
#pragma unroll
    for (int t = 0; t < 4; t++) {
      int idx = tid + t * 256;
      int row = idx >> 4, kk2 = idx & 15;
      const float2 ea = *(const float2*)(emb + si[row] * DM + k0 + 2 * kk2);
      const float2 eb = *(const float2*)(emb + sj[row] * DM + k0 + 2 * kk2);
      float p0 = ea.x * eb.x, p1 = ea.y * eb.y;
      __nv_bfloat16 h0 = __float2bfloat16(p0);
      __nv_bfloat16 h1 = __float2bfloat16(p1);
      __nv_bfloat16 l0 = __float2bfloat16(p0 - __bfloat162float(h0));
      __nv_bfloat16 l1 = __float2bfloat16(p1 - __bfloat162float(h1));
      uint32_t hp = ((uint32_t)*(uint16_t*)&h1 << 16) | *(uint16_t*)&h0;
      uint32_t lp = ((uint32_t)*(uint16_t*)&l1 << 16) | *(uint16_t*)&l0;
      *(uint32_t*)(smem + OFF_A_HI + row * 80 + kk2 * 4) = hp;
      *(uint32_t*)(smem + OFF_A_LO + row * 80 + kk2 * 4) = lp;
    }
    // B: 256x32 of pre-split W1^T (1024 uint4 -> 4 iters)
#pragma unroll
    for (int t = 0; t < 4; t++) {
      int idx = tid + t * 256;
      int n = idx >> 2, kg = idx & 3;
      uint4 hv = *(const uint4*)(g_w1t_hi + n * DM + k0 + kg * 8);
      uint4 lv = *(const uint4*)(g_w1t_lo + n * DM + k0 + kg * 8);
      *(uint4*)(smem + OFF_B_HI + n * 80 + kg * 16) = hv;
      *(uint4*)(smem + OFF_B_LO + n * 80 + kg * 16) = lv;
    }
    __syncthreads();

#pragma unroll
    for (int ks = 0; ks < 2; ks++) {
      uint32_t ah[2][4], al[2][4], bb[8][2];
      int arow = (lane & 7) + ((lane >> 3) & 1) * 8;
      int acolb = ks * 32 + ((lane >> 4) << 4);
#pragma unroll
      for (int mt = 0; mt < 2; mt++) {
        uint32_t ra = (uint32_t)((wm * 32 + mt * 16 + arow) * 80 + acolb);
        ldsm_x4(ah[mt], sb + OFF_A_HI + ra);
        ldsm_x4(al[mt], sb + OFF_A_LO + ra);
      }
      int bl_ = lane & 15;
      int brow = bl_ & 7;
      int bcolb = ks * 32 + ((bl_ >> 3) << 4);
#pragma unroll
      for (int nt = 0; nt < 8; nt++) {
        uint32_t rb = (uint32_t)((wn * 64 + nt * 8 + brow) * 80 + bcolb);
        ldsm_x2(bb[nt], sb + OFF_B_HI + rb);
      }
#pragma unroll
      for (int mt = 0; mt < 2; mt++)
#pragma unroll
        for (int nt = 0; nt < 8; nt++) mma16816(acc[mt][nt], ah[mt], bb[nt]);
#pragma unroll
      for (int mt = 0; mt < 2; mt++)
#pragma unroll
        for (int nt = 0; nt < 8; nt++) mma16816(acc[mt][nt], al[mt], bb[nt]);
#pragma unroll
      for (int nt = 0; nt < 8; nt++) {
        uint32_t rb = (uint32_t)((wn * 64 + nt * 8 + brow) * 80 + bcolb);
        ldsm_x2(bb[nt], sb + OFF_B_LO + rb);
      }
#pragma unroll
      for (int mt = 0; mt < 2; mt++)
#pragma unroll
        for (int nt = 0; nt < 8; nt++) mma16816(acc[mt][nt], ah[mt], bb[nt]);
    }
    __syncthreads();
  }

#pragma unroll
  for (int mt = 0; mt < 2; mt++) {
#pragma unroll
    for (int half = 0; half < 2; half++) {
      float s = 0.f;
#pragma unroll
      for (int nt = 0; nt < 8; nt++) {
        int col = wn * 64 + nt * 8 + 2 * (lane & 3);
        float h0 = acc[mt][nt][half * 2 + 0] + b1s[col];
        float h1 = acc[mt][nt][half * 2 + 1] + b1s[col + 1];
        s = fmaf(fmaxf(h0, 0.f), w2s[col], s);
        s = fmaf(fmaxf(h1, 0.f), w2s[col + 1], s);
      }
      s += __shfl_xor_sync(0xffffffffu, s, 1);
      s += __shfl_xor_sync(0xffffffffu, s, 2);
      if ((lane & 3) == 0) {
        int row = wm * 32 + mt * 16 + half * 8 + (lane >> 2);
        red[row * 4 + wn] = s;
      }
    }
  }
  __syncthreads();
  if (tid < PT) {
    int k = tile * PT + tid;
    if (k < NPAIR) {
      float s = red[tid * 4] + red[tid * 4 + 1] + red[tid * 4 + 2] +
                red[tid * 4 + 3] + b2[0];
      float t = tanhf(s);
      int i = si[tid], j = sj[tid];
      g_R[(size_t)b * NA * NA + i * NA + j] = t;
      g_R[(size_t)b * NA * NA + j * NA + i] = t;
    }
  }
}

// ---------------------------------------------------------------------------
// PSD projection via HYBRID matrix-sign iteration (no eigensolver):
//   Phase 1 (13 quintic iters), Phase 2 (4 cubic polish iters),
//   per-iteration symmetrization. R_psd = 0.5(X + X*S) + eps*I.
// ---------------------------------------------------------------------------
#define QI 13
#define CI 4
#define QA 3.4445f
#define QB (-4.7750f)
#define QC 2.0315f
#define NSD 112
#define NS_THREADS 448
#define NS_TRI (NSD * (NSD + 1) / 2)
#define O_S32 0
#define O_SHI 50176
#define O_SLO 77056
#define O_YHI 103936
#define O_YLO 130816
#define O_THI 157696
#define O_TLO 184576
#define O_AUX 211456
#define SMEM_NS (211456 + 512 + 64)

__device__ __forceinline__ void gemm_ab(uint32_t sb, uint32_t oAh, uint32_t oAl,
                                        uint32_t oBh, uint32_t oBl,
                                        int wm, int wn, int lane,
                                        float (&acc)[7][4]) {
#pragma unroll
  for (int nt = 0; nt < 7; nt++)
#pragma unroll
    for (int e = 0; e < 4; e++) acc[nt][e] = 0.f;
#pragma unroll
  for (int ks = 0; ks < 7; ks++) {
    uint32_t ah[4], al[4], bb[7][2];
    int arow = (lane & 7) + ((lane >> 3) & 1) * 8;
    uint32_t ra = (uint32_t)((wm * 16 + arow) * 240 + ks * 32 + ((lane >> 4) << 4));
    ldsm_x4(ah, sb + oAh + ra);
    ldsm_x4(al, sb + oAl + ra);
    int bl_ = lane & 15;
    int brow = bl_ & 7;
    int bco = ks * 32 + ((bl_ >> 3) << 4);
#pragma unroll
    for (int nt = 0; nt < 7; nt++) {
      uint32_t rb = (uint32_t)((wn * 56 + nt * 8 + brow) * 240 + bco);
      ldsm_x2(bb[nt], sb + oBh + rb);
    }
#pragma unroll
    for (int nt = 0; nt < 7; nt++) mma16816(acc[nt], ah, bb[nt]);
#pragma unroll
    for (int nt = 0; nt < 7; nt++) mma16816(acc[nt], al, bb[nt]);
#pragma unroll
    for (int nt = 0; nt < 7; nt++) {
      uint32_t rb = (uint32_t)((wn * 56 + nt * 8 + brow) * 240 + bco);
      ldsm_x2(bb[nt], sb + oBl + rb);
    }
#pragma unroll
    for (int nt = 0; nt < 7; nt++) mma16816(acc[nt], ah, bb[nt]);
  }
}

__global__ __launch_bounds__(NS_THREADS) void psd_kernel(float* __restrict__ out) {
  extern __shared__ char smem[];
  uint32_t sb = smem_u32(smem);
  float* S32 = (float*)(smem + O_S32);
  float* aux = (float*)(smem + O_AUX);
  int b = blockIdx.x;
  int tid = threadIdx.x, lane = tid & 31, warp = tid >> 5;
  int wm = warp % 7, wn = warp / 7;
  const float* Rg = g_R + (size_t)b * NA * NA;

  float part = 0.f;
  for (int idx = tid; idx < NSD * NSD; idx += NS_THREADS) {
    int r = idx / NSD, c = idx - (idx / NSD) * NSD;
    float v = 0.f;
    if (r < NA && c < NA) v = (r == c) ? (1.0f - 1e-4f) : Rg[r * NA + c];
    S32[idx] = v;
    part += v * v;
  }
#pragma unroll
  for (int o = 16; o; o >>= 1) part += __shfl_xor_sync(0xffffffffu, part, o);
  if (lane == 0) aux[warp] = part;
  __syncthreads();
  if (tid == 0) {
    float s = 0.f;
    for (int w = 0; w < 14; w++) s += aux[w];
    float f = sqrtf(s);
    aux[14] = f;
    aux[15] = 1.0f / f;
  }
  __syncthreads();
  float fnorm = aux[14], invf = aux[15];

  for (int idx = tid; idx < NSD * NSD; idx += NS_THREADS) {
    int r = idx / NSD, c = idx - (idx / NSD) * NSD;
    float v = S32[idx] * invf;
    S32[idx] = v;
    __nv_bfloat16 h = __float2bfloat16(v);
    __nv_bfloat16 l = __float2bfloat16(v - __bfloat162float(h));
    uint32_t off = (uint32_t)(r * 240 + c * 2);
    *(__nv_bfloat16*)(smem + O_SHI + off) = h;
    *(__nv_bfloat16*)(smem + O_SLO + off) = l;
  }
  __syncthreads();

  float acc[7][4];

  // Phase 1: quintic
  for (int it = 0; it < QI; it++) {
    gemm_ab(sb, O_SHI, O_SLO, O_SHI, O_SLO, wm, wn, lane, acc);
#pragma unroll
    for (int nt = 0; nt < 7; nt++) {
#pragma unroll
      for (int half = 0; half < 2; half++) {
        int row = wm * 16 + (lane >> 2) + half * 8;
        int col = wn * 56 + nt * 8 + 2 * (lane & 3);
        float a0 = acc[nt][half * 2 + 0], a1 = acc[nt][half * 2 + 1];
        __nv_bfloat16 h0 = __float2bfloat16(a0), h1 = __float2bfloat16(a1);
        float r0 = a0 - __bfloat162float(h0), r1 = a1 - __bfloat162float(h1);
        uint32_t hp = ((uint32_t)*(uint16_t*)&h1 << 16) | *(uint16_t*)&h0;
        uint32_t lp = pack_bf16(r0, r1);
        *(uint32_t*)(smem + O_YHI + row * 240 + col * 2) = hp;
        *(uint32_t*)(smem + O_YLO + row * 240 + col * 2) = lp;
      }
    }
    __syncthreads();
    gemm_ab(sb, O_YHI, O_YLO, O_YHI, O_YLO, wm, wn, lane, acc);
    __syncthreads();
#pragma unroll
    for (int nt = 0; nt < 7; nt++) {
#pragma unroll
      for (int half = 0; half < 2; half++) {
        int row = wm * 16 + (lane >> 2) + half * 8;
        int col = wn * 56 + nt * 8 + 2 * (lane & 3);
        float t01[2];
#pragma unroll
        for (int j = 0; j < 2; j++) {
          int c = col + j;
          uint32_t off = (uint32_t)(row * 240 + c * 2);
          float y = __bfloat162float(*(__nv_bfloat16*)(smem + O_YHI + off)) +
                    __bfloat162float(*(__nv_bfloat16*)(smem + O_YLO + off));
          t01[j] = ((row == c) ? QA : 0.f) + QB * y + QC * acc[nt][half * 2 + j];
        }
        __nv_bfloat16 h0 = __float2bfloat16(t01[0]), h1 = __float2bfloat16(t01[1]);
        float r0 = t01[0] - __bfloat162float(h0), r1 = t01[1] - __bfloat162float(h1);
        uint32_t hp = ((uint32_t)*(uint16_t*)&h1 << 16) | *(uint16_t*)&h0;
        uint32_t lp = pack_bf16(r0, r1);
        *(uint32_t*)(smem + O_THI + row * 240 + col * 2) = hp;
        *(uint32_t*)(smem + O_TLO + row * 240 + col * 2) = lp;
      }
    }
    __syncthreads();
    gemm_ab(sb, O_SHI, O_SLO, O_THI, O_TLO, wm, wn, lane, acc);
    __syncthreads();
#pragma unroll
    for (int nt = 0; nt < 7; nt++) {
#pragma unroll
      for (int half = 0; half < 2; half++) {
        int row = wm * 16 + (lane >> 2) + half * 8;
        int col = wn * 56 + nt * 8 + 2 * (lane & 3);
        int i0 = row * NSD + col;
        S32[i0]     = acc[nt][half * 2 + 0];
        S32[i0 + 1] = acc[nt][half * 2 + 1];
      }
    }
    __syncthreads();
    for (int idx = tid; idx < NS_TRI; idx += NS_THREADS) {
      int i = (int)((sqrtf(8.f * (float)idx + 1.f) - 1.f) * 0.5f);
      while (i * (i + 1) / 2 > idx) i--;
      while ((i + 1) * (i + 2) / 2 <= idx) i++;
      int j = idx - i * (i + 1) / 2;
      float avg = 0.5f * (S32[i * NSD + j] + S32[j * NSD + i]);
      avg = fminf(fmaxf(avg, -2.f), 2.f);
      S32[i * NSD + j] = avg;
      S32[j * NSD + i] = avg;
      __nv_bfloat16 h = __float2bfloat16(avg);
      __nv_bfloat16 l = __float2bfloat16(avg - __bfloat162float(h));
      uint32_t oij = (uint32_t)(i * 240 + j * 2);
      uint32_t oji = (uint32_t)(j * 240 + i * 2);
      *(__nv_bfloat16*)(smem + O_SHI + oij) = h;
      *(__nv_bfloat16*)(smem + O_SLO + oij) = l;
      *(__nv_bfloat16*)(smem + O_SHI + oji) = h;
      *(__nv_bfloat16*)(smem + O_SLO + oji) = l;
    }
    __syncthreads();
  }

  // Phase 2: cubic polish
  for (int it = 0; it < CI; it++) {
    gemm_ab(sb, O_SHI, O_SLO, O_SHI, O_SLO, wm, wn, lane, acc);
#pragma unroll
    for (int nt = 0; nt < 7; nt++) {
#pragma unroll
      for (int half = 0; half < 2; half++) {
        int row = wm * 16 + (lane >> 2) + half * 8;
        int col = wn * 56 + nt * 8 + 2 * (lane & 3);
        float a0 = acc[nt][half * 2 + 0], a1 = acc[nt][half * 2 + 1];
        __nv_bfloat16 h0 = __float2bfloat16(a0), h1 = __float2bfloat16(a1);
        float r0 = a0 - __bfloat162float(h0), r1 = a1 - __bfloat162float(h1);
        uint32_t hp = ((uint32_t)*(uint16_t*)&h1 << 16) | *(uint16_t*)&h0;
        uint32_t lp = pack_bf16(r0, r1);
        *(uint32_t*)(smem + O_YHI + row * 240 + col * 2) = hp;
        *(uint32_t*)(smem + O_YLO + row * 240 + col * 2) = lp;
      }
    }
    __syncthreads();
    gemm_ab(sb, O_SHI, O_SLO, O_YHI, O_YLO, wm, wn, lane, acc);
    __syncthreads();
#pragma unroll
    for (int nt = 0; nt < 7; nt++) {
#pragma unroll
      for (int half = 0; half < 2; half++) {
        int row = wm * 16 + (lane >> 2) + half * 8;
        int col = wn * 56 + nt * 8 + 2 * (lane & 3);
        int i0 = row * NSD + col;
        S32[i0]     = 1.5f * S32[i0]     - 0.5f * acc[nt][half * 2 + 0];
        S32[i0 + 1] = 1.5f * S32[i0 + 1] - 0.5f * acc[nt][half * 2 + 1];
      }
    }
    __syncthreads();
    for (int idx = tid; idx < NS_TRI; idx += NS_THREADS) {
      int i = (int)((sqrtf(8.f * (float)idx + 1.f) - 1.f) * 0.5f);
      while (i * (i + 1) / 2 > idx) i--;
      while ((i + 1) * (i + 2) / 2 <= idx) i++;
      int j = idx - i * (i + 1) / 2;
      float avg = 0.5f * (S32[i * NSD + j] + S32[j * NSD + i]);
      avg = fminf(fmaxf(avg, -2.f), 2.f);
      S32[i * NSD + j] = avg;
      S32[j * NSD + i] = avg;
      __nv_bfloat16 h = __float2bfloat16(avg);
      __nv_bfloat16 l = __float2bfloat16(avg - __bfloat162float(h));
      uint32_t oij = (uint32_t)(i * 240 + j * 2);
      uint32_t oji = (uint32_t)(j * 240 + i * 2);
      *(__nv_bfloat16*)(smem + O_SHI + oij) = h;
      *(__nv_bfloat16*)(smem + O_SLO + oij) = l;
      *(__nv_bfloat16*)(smem + O_SHI + oji) = h;
      *(__nv_bfloat16*)(smem + O_SLO + oji) = l;
    }
    __syncthreads();
  }

  // final: W = S*Xn ; P = 0.5(X + f*W) + eps*I
  for (int idx = tid; idx < NSD * NSD; idx += NS_THREADS) {
    int r = idx / NSD, c = idx - (idx / NSD) * NSD;
    float v = 0.f;
    if (r < NA && c < NA)
      v = ((r == c) ? (1.0f - 1e-4f) : Rg[r * NA + c]) * invf;
    __nv_bfloat16 h = __float2bfloat16(v);
    __nv_bfloat16 l = __float2bfloat16(v - __bfloat162float(h));
    uint32_t off = (uint32_t)(r * 240 + c * 2);
    *(__nv_bfloat16*)(smem + O_YHI + off) = h;
    *(__nv_bfloat16*)(smem + O_YLO + off) = l;
  }
  __syncthreads();
  gemm_ab(sb, O_SHI, O_SLO, O_YHI, O_YLO, wm, wn, lane, acc);
  __syncthreads();
#pragma unroll
  for (int nt = 0; nt < 7; nt++) {
#pragma unroll
    for (int half = 0; half < 2; half++) {
      int row = wm * 16 + (lane >> 2) + half * 8;
      int col = wn * 56 + nt * 8 + 2 * (lane & 3);
#pragma unroll
      for (int j = 0; j < 2; j++) {
        int c = col + j;
        float Xg = 0.f;
        if (row < NA && c < NA)
          Xg = (row == c) ? (1.0f - 1e-4f) : Rg[row * NA + c];
        float P = 0.5f * (Xg + fnorm * acc[nt][half * 2 + j]) +
                  ((row == c) ? 1e-4f : 0.f);
        S32[row * NSD + c] = P;
      }
    }
  }
  __syncthreads();

  if (tid < NA) aux[16 + tid] = rsqrtf(fmaxf(S32[tid * (NSD + 1)], 1e-6f));
  __syncthreads();

  const float* vl = g_vols + b * NA;
  float* og = out + (size_t)b * NA * NA;
  for (int idx = tid; idx < NA * NA; idx += NS_THREADS) {
    int r = idx / NA, c = idx - (idx / NA) * NA;
    og[idx] = vl[r] * vl[c] * aux[16 + r] * aux[16 + c] * S32[r * NSD + c];
  }
}

// ---------------------------------------------------------------------------
extern "C" void kernel_launch(void* const* d_in, const int* in_sizes, int n_in,
                              void* d_out, int out_size) {
  const float* x   = (const float*)d_in[0];
  const float* vw1 = (const float*)d_in[1];
  const float* vb1 = (const float*)d_in[2];
  const float* vw2 = (const float*)d_in[3];
  const float* vb2 = (const float*)d_in[4];
  const float* cw1 = (const float*)d_in[5];
  const float* cb1 = (const float*)d_in[6];
  const float* cw2 = (const float*)d_in[7];
  const float* cb2 = (const float*)d_in[8];
  float* out = (float*)d_out;

  prep_w1t<<<HID, DM>>>(cw1);
  vols_kernel<<<dim3(7, BATCH), 256>>>(x, vw1, vb1, vw2, vb2);

  cudaFuncSetAttribute(pair_mma_kernel,
                       cudaFuncAttributeMaxDynamicSharedMemorySize, SMEM_PAIR);
  pair_mma_kernel<<<dim3(PTILES, BATCH), 256, SMEM_PAIR>>>(x, cb1, cw2, cb2);

  cudaFuncSetAttribute(psd_kernel,
                       cudaFuncAttributeMaxDynamicSharedMemorySize, SMEM_NS);
  psd_kernel<<<BATCH, NS_THREADS, SMEM_NS>>>(out);
}

// round 13
// speedup vs baseline: 3.6255x; 1.0801x over previous
#include <cuda_runtime.h>
#include <cuda_bf16.h>
#include <math.h>
#include <stdint.h>

#define NA 100
#define DM 256
#define HID 256
#define BATCH 64
#define NPAIR 4950
#define PT 64           // pairs per CTA tile
#define PTILES 78       // ceil(4950/64)
#define VTILES 7        // vols row-groups of 16

// ---------------- device scratch (no allocation allowed) ----------------
__device__ float g_R[BATCH * NA * NA];
__device__ float g_vols[BATCH * NA];
__device__ __nv_bfloat16 g_w1t_hi[HID * DM];  // [n][k] K-major
__device__ __nv_bfloat16 g_w1t_lo[HID * DM];

__device__ __forceinline__ uint32_t smem_u32(const void* p) {
  uint32_t a;
  asm("{ .reg .u64 t; cvta.to.shared.u64 t, %1; cvt.u32.u64 %0, t; }"
      : "=r"(a) : "l"(p));
  return a;
}
__device__ __forceinline__ void ldsm_x4(uint32_t (&r)[4], uint32_t addr) {
  asm volatile(
      "ldmatrix.sync.aligned.m8n8.x4.shared.b16 {%0,%1,%2,%3}, [%4];"
      : "=r"(r[0]), "=r"(r[1]), "=r"(r[2]), "=r"(r[3]) : "r"(addr));
}
__device__ __forceinline__ void ldsm_x2(uint32_t (&r)[2], uint32_t addr) {
  asm volatile(
      "ldmatrix.sync.aligned.m8n8.x2.shared.b16 {%0,%1}, [%2];"
      : "=r"(r[0]), "=r"(r[1]) : "r"(addr));
}
__device__ __forceinline__ void mma16816(float (&d)[4], const uint32_t (&a)[4],
                                         const uint32_t (&b)[2]) {
  asm volatile(
      "mma.sync.aligned.m16n8k16.row.col.f32.bf16.bf16.f32 "
      "{%0,%1,%2,%3}, {%4,%5,%6,%7}, {%8,%9}, {%0,%1,%2,%3};"
      : "+f"(d[0]), "+f"(d[1]), "+f"(d[2]), "+f"(d[3])
      : "r"(a[0]), "r"(a[1]), "r"(a[2]), "r"(a[3]), "r"(b[0]), "r"(b[1]));
}
__device__ __forceinline__ uint32_t pack_bf16(float a, float b) {
  __nv_bfloat16 h0 = __float2bfloat16(a), h1 = __float2bfloat16(b);
  return ((uint32_t)*(uint16_t*)&h1 << 16) | *(uint16_t*)&h0;
}

// ---------------------------------------------------------------------------
__global__ void prep_w1t(const float* __restrict__ w1) {
  int n = blockIdx.x, k = threadIdx.x;
  float v = w1[k * HID + n];
  __nv_bfloat16 h = __float2bfloat16(v);
  float r = v - __bfloat162float(h);
  g_w1t_hi[n * DM + k] = h;
  g_w1t_lo[n * DM + k] = __float2bfloat16(r);
}

// ---------------------------------------------------------------------------
// FUSED pair MLP (tiles 0..77) + vols MLP (tiles 78..84), per batch.
// pair: mma.sync bf16 2-way split, 3 passes, 2 CTAs/SM.
// ---------------------------------------------------------------------------
#define OFF_A_HI 0
#define OFF_A_LO 5120
#define OFF_B_HI 10240
#define OFF_B_LO 30720
#define OFF_SI   51200
#define OFF_SJ   51456
#define OFF_B1   51712
#define OFF_W2   52736
#define OFF_RED  53760
#define SMEM_PAIR 54784

__global__ __launch_bounds__(256, 2) void pair_mma_kernel(
    const float* __restrict__ x,
    const float* __restrict__ vw1, const float* __restrict__ vb1,
    const float* __restrict__ vw2, const float* __restrict__ vb2,
    const float* __restrict__ b1, const float* __restrict__ w2,
    const float* __restrict__ b2) {
  extern __shared__ char smem[];
  uint32_t sb = smem_u32(smem);
  int b = blockIdx.y, tile = blockIdx.x;
  int tid = threadIdx.x, lane = tid & 31, warp = tid >> 5;
  const float* emb = x + ((size_t)b * 64 + 63) * NA * DM;

  if (tile >= PTILES) {
    // ================= vols branch =================
    int r0 = (tile - PTILES) * 16;
    float* es = (float*)smem;                  // [16][256]
    float* red = (float*)(smem + 16 * DM * 4); // [16][8]

    for (int idx = tid; idx < 16 * DM; idx += 256) {
      int r = idx >> 8, d = idx & 255;
      es[r * DM + d] = (r0 + r < NA) ? emb[(r0 + r) * DM + d] : 0.f;
    }
    __syncthreads();

    float acc[16];
    float bb = vb1[tid];
#pragma unroll
    for (int r = 0; r < 16; r++) acc[r] = bb;

#pragma unroll 4
    for (int d = 0; d < DM; d++) {
      float w = vw1[d * HID + tid];
#pragma unroll
      for (int r = 0; r < 16; r++) acc[r] = fmaf(es[r * DM + d], w, acc[r]);
    }

    float wv = vw2[tid];
#pragma unroll
    for (int r = 0; r < 16; r++) {
      float v = fmaxf(acc[r], 0.f) * wv;
#pragma unroll
      for (int o = 16; o; o >>= 1) v += __shfl_xor_sync(0xffffffffu, v, o);
      if (lane == 0) red[r * 8 + warp] = v;
    }
    __syncthreads();
    if (tid < 16) {
      float s = 0.f;
#pragma unroll
      for (int w = 0; w < 8; w++) s += red[tid * 8 + w];
      s += vb2[0];
      float sp = fmaxf(s, 0.f) + log1pf(expf(-fabsf(s)));
      if (r0 + tid < NA) g_vols[b * NA + r0 + tid] = sp + 1e-6f;
    }
    return;
  }

  // ================= pair branch =================
  int wm = warp >> 2, wn = warp & 3;   // 2 x 4 warps

  int* si = (int*)(smem + OFF_SI);
  int* sj = (int*)(smem + OFF_SJ);
  float* b1s = (float*)(smem + OFF_B1);
  float* w2s = (float*)(smem + OFF_W2);
  float* red = (float*)(smem + OFF_RED);

  if (tid < PT) {
    int k = tile * PT + tid;
    if (k >= NPAIR) k = NPAIR - 1;
    int i = (int)((1.0f + sqrtf(1.0f + 8.0f * (float)k)) * 0.5f);
    while ((i * (i - 1)) / 2 > k) i--;
    while (((i + 1) * i) / 2 <= k) i++;
    si[tid] = i;
    sj[tid] = k - (i * (i - 1)) / 2;
  }
  b1s[tid] = b1[tid];
  w2s[tid] = w2[tid];
  __syncthreads();

  float acc[2][8][4];
#pragma unroll
  for (int mt = 0; mt < 2; mt++)
#pragma unroll
    for (int nt = 0; nt < 8; nt++)
#pragma unroll
      for (int e = 0; e < 4; e++) acc[mt][nt][e] = 0.f;

  for (int ch = 0; ch < 8; ch++) {
    int k0 = ch * 32;
#pragma unroll
    for (int t = 0; t < 4; t++) {
      int idx = tid + t * 256;
      int row = idx >> 4, kk2 = idx & 15;
      const float2 ea = *(const float2*)(emb + si[row] * DM + k0 + 2 * kk2);
      const float2 eb = *(const float2*)(emb + sj[row] * DM + k0 + 2 * kk2);
      float p0 = ea.x * eb.x, p1 = ea.y * eb.y;
      __nv_bfloat16 h0 = __float2bfloat16(p0);
      __nv_bfloat16 h1 = __float2bfloat16(p1);
      __nv_bfloat16 l0 = __float2bfloat16(p0 - __bfloat162float(h0));
      __nv_bfloat16 l1 = __float2bfloat16(p1 - __bfloat162float(h1));
      uint32_t hp = ((uint32_t)*(uint16_t*)&h1 << 16) | *(uint16_t*)&h0;
      uint32_t lp = ((uint32_t)*(uint16_t*)&l1 << 16) | *(uint16_t*)&l0;
      *(uint32_t*)(smem + OFF_A_HI + row * 80 + kk2 * 4) = hp;
      *(uint32_t*)(smem + OFF_A_LO + row * 80 + kk2 * 4) = lp;
    }
#pragma unroll
    for (int t = 0; t < 4; t++) {
      int idx = tid + t * 256;
      int n = idx >> 2, kg = idx & 3;
      uint4 hv = *(const uint4*)(g_w1t_hi + n * DM + k0 + kg * 8);
      uint4 lv = *(const uint4*)(g_w1t_lo + n * DM + k0 + kg * 8);
      *(uint4*)(smem + OFF_B_HI + n * 80 + kg * 16) = hv;
      *(uint4*)(smem + OFF_B_LO + n * 80 + kg * 16) = lv;
    }
    __syncthreads();

#pragma unroll
    for (int ks = 0; ks < 2; ks++) {
      uint32_t ah[2][4], al[2][4], bb[8][2];
      int arow = (lane & 7) + ((lane >> 3) & 1) * 8;
      int acolb = ks * 32 + ((lane >> 4) << 4);
#pragma unroll
      for (int mt = 0; mt < 2; mt++) {
        uint32_t ra = (uint32_t)((wm * 32 + mt * 16 + arow) * 80 + acolb);
        ldsm_x4(ah[mt], sb + OFF_A_HI + ra);
        ldsm_x4(al[mt], sb + OFF_A_LO + ra);
      }
      int bl_ = lane & 15;
      int brow = bl_ & 7;
      int bcolb = ks * 32 + ((bl_ >> 3) << 4);
#pragma unroll
      for (int nt = 0; nt < 8; nt++) {
        uint32_t rb = (uint32_t)((wn * 64 + nt * 8 + brow) * 80 + bcolb);
        ldsm_x2(bb[nt], sb + OFF_B_HI + rb);
      }
#pragma unroll
      for (int mt = 0; mt < 2; mt++)
#pragma unroll
        for (int nt = 0; nt < 8; nt++) mma16816(acc[mt][nt], ah[mt], bb[nt]);
#pragma unroll
      for (int mt = 0; mt < 2; mt++)
#pragma unroll
        for (int nt = 0; nt < 8; nt++) mma16816(acc[mt][nt], al[mt], bb[nt]);
#pragma unroll
      for (int nt = 0; nt < 8; nt++) {
        uint32_t rb = (uint32_t)((wn * 64 + nt * 8 + brow) * 80 + bcolb);
        ldsm_x2(bb[nt], sb + OFF_B_LO + rb);
      }
#pragma unroll
      for (int mt = 0; mt < 2; mt++)
#pragma unroll
        for (int nt = 0; nt < 8; nt++) mma16816(acc[mt][nt], ah[mt], bb[nt]);
    }
    __syncthreads();
  }

#pragma unroll
  for (int mt = 0; mt < 2; mt++) {
#pragma unroll
    for (int half = 0; half < 2; half++) {
      float s = 0.f;
#pragma unroll
      for (int nt = 0; nt < 8; nt++) {
        int col = wn * 64 + nt * 8 + 2 * (lane & 3);
        float h0 = acc[mt][nt][half * 2 + 0] + b1s[col];
        float h1 = acc[mt][nt][half * 2 + 1] + b1s[col + 1];
        s = fmaf(fmaxf(h0, 0.f), w2s[col], s);
        s = fmaf(fmaxf(h1, 0.f), w2s[col + 1], s);
      }
      s += __shfl_xor_sync(0xffffffffu, s, 1);
      s += __shfl_xor_sync(0xffffffffu, s, 2);
      if ((lane & 3) == 0) {
        int row = wm * 32 + mt * 16 + half * 8 + (lane >> 2);
        red[row * 4 + wn] = s;
      }
    }
  }
  __syncthreads();
  if (tid < PT) {
    int k = tile * PT + tid;
    if (k < NPAIR) {
      float s = red[tid * 4] + red[tid * 4 + 1] + red[tid * 4 + 2] +
                red[tid * 4 + 3] + b2[0];
      float t = tanhf(s);
      int i = si[tid], j = sj[tid];
      g_R[(size_t)b * NA * NA + i * NA + j] = t;
      g_R[(size_t)b * NA * NA + j * NA + i] = t;
    }
  }
}

// ---------------------------------------------------------------------------
// PSD projection via HYBRID matrix-sign iteration:
//   11 quintic iters (symmetrize each), 4 cubic iters (symmetrize odd only),
//   R_psd = 0.5(X + X*S) + eps*I.  112^3 bf16 hi/lo 3-pass GEMMs.
// ---------------------------------------------------------------------------
#define QI 11
#define CI 4
#define QA 3.4445f
#define QB (-4.7750f)
#define QC 2.0315f
#define NSD 112
#define NS_THREADS 448
#define NS_TRI (NSD * (NSD + 1) / 2)
#define NPK 15
#define O_S32 0
#define O_SHI 50176
#define O_SLO 77056
#define O_YHI 103936
#define O_YLO 130816
#define O_THI 157696
#define O_TLO 184576
#define O_AUX 211456
#define SMEM_NS (211456 + 512 + 64)

__device__ __forceinline__ void gemm_ab(uint32_t sb, uint32_t oAh, uint32_t oAl,
                                        uint32_t oBh, uint32_t oBl,
                                        int wm, int wn, int lane,
                                        float (&acc)[7][4]) {
#pragma unroll
  for (int nt = 0; nt < 7; nt++)
#pragma unroll
    for (int e = 0; e < 4; e++) acc[nt][e] = 0.f;
#pragma unroll
  for (int ks = 0; ks < 7; ks++) {
    uint32_t ah[4], al[4], bb[7][2];
    int arow = (lane & 7) + ((lane >> 3) & 1) * 8;
    uint32_t ra = (uint32_t)((wm * 16 + arow) * 240 + ks * 32 + ((lane >> 4) << 4));
    ldsm_x4(ah, sb + oAh + ra);
    ldsm_x4(al, sb + oAl + ra);
    int bl_ = lane & 15;
    int brow = bl_ & 7;
    int bco = ks * 32 + ((bl_ >> 3) << 4);
#pragma unroll
    for (int nt = 0; nt < 7; nt++) {
      uint32_t rb = (uint32_t)((wn * 56 + nt * 8 + brow) * 240 + bco);
      ldsm_x2(bb[nt], sb + oBh + rb);
    }
#pragma unroll
    for (int nt = 0; nt < 7; nt++) mma16816(acc[nt], ah, bb[nt]);
#pragma unroll
    for (int nt = 0; nt < 7; nt++) mma16816(acc[nt], al, bb[nt]);
#pragma unroll
    for (int nt = 0; nt < 7; nt++) {
      uint32_t rb = (uint32_t)((wn * 56 + nt * 8 + brow) * 240 + bco);
      ldsm_x2(bb[nt], sb + oBl + rb);
    }
#pragma unroll
    for (int nt = 0; nt < 7; nt++) mma16816(acc[nt], ah, bb[nt]);
  }
}

__global__ __launch_bounds__(NS_THREADS) void psd_kernel(float* __restrict__ out) {
  extern __shared__ char smem[];
  uint32_t sb = smem_u32(smem);
  float* S32 = (float*)(smem + O_S32);
  float* aux = (float*)(smem + O_AUX);
  int b = blockIdx.x;
  int tid = threadIdx.x, lane = tid & 31, warp = tid >> 5;
  int wm = warp % 7, wn = warp / 7;
  const float* Rg = g_R + (size_t)b * NA * NA;

  // precompute this thread's symmetrize pair indices (fixed across iters)
  int psi[NPK], psj[NPK];
#pragma unroll
  for (int k = 0; k < NPK; k++) {
    int idx = tid + k * NS_THREADS;
    if (idx < NS_TRI) {
      int i = (int)((sqrtf(8.f * (float)idx + 1.f) - 1.f) * 0.5f);
      while (i * (i + 1) / 2 > idx) i--;
      while ((i + 1) * (i + 2) / 2 <= idx) i++;
      psi[k] = i;
      psj[k] = idx - i * (i + 1) / 2;
    } else {
      psi[k] = 0;
      psj[k] = 0;
    }
  }

#define SYMMETRIZE_REFRESH()                                                  \
  do {                                                                        \
    _Pragma("unroll")                                                         \
    for (int k = 0; k < NPK; k++) {                                           \
      if (tid + k * NS_THREADS < NS_TRI) {                                    \
        int i = psi[k], j = psj[k];                                           \
        float avg = 0.5f * (S32[i * NSD + j] + S32[j * NSD + i]);             \
        avg = fminf(fmaxf(avg, -2.f), 2.f);                                   \
        S32[i * NSD + j] = avg;                                               \
        S32[j * NSD + i] = avg;                                               \
        __nv_bfloat16 h = __float2bfloat16(avg);                              \
        __nv_bfloat16 l = __float2bfloat16(avg - __bfloat162float(h));        \
        uint32_t oij = (uint32_t)(i * 240 + j * 2);                           \
        uint32_t oji = (uint32_t)(j * 240 + i * 2);                           \
        *(__nv_bfloat16*)(smem + O_SHI + oij) = h;                            \
        *(__nv_bfloat16*)(smem + O_SLO + oij) = l;                            \
        *(__nv_bfloat16*)(smem + O_SHI + oji) = h;                            \
        *(__nv_bfloat16*)(smem + O_SLO + oji) = l;                            \
      }                                                                       \
    }                                                                         \
  } while (0)

  float part = 0.f;
  for (int idx = tid; idx < NSD * NSD; idx += NS_THREADS) {
    int r = idx / NSD, c = idx - (idx / NSD) * NSD;
    float v = 0.f;
    if (r < NA && c < NA) v = (r == c) ? (1.0f - 1e-4f) : Rg[r * NA + c];
    S32[idx] = v;
    part += v * v;
  }
#pragma unroll
  for (int o = 16; o; o >>= 1) part += __shfl_xor_sync(0xffffffffu, part, o);
  if (lane == 0) aux[warp] = part;
  __syncthreads();
  if (tid == 0) {
    float s = 0.f;
    for (int w = 0; w < 14; w++) s += aux[w];
    float f = sqrtf(s);
    aux[14] = f;
    aux[15] = 1.0f / f;
  }
  __syncthreads();
  float fnorm = aux[14], invf = aux[15];

  for (int idx = tid; idx < NSD * NSD; idx += NS_THREADS) {
    int r = idx / NSD, c = idx - (idx / NSD) * NSD;
    float v = S32[idx] * invf;
    S32[idx] = v;
    __nv_bfloat16 h = __float2bfloat16(v);
    __nv_bfloat16 l = __float2bfloat16(v - __bfloat162float(h));
    uint32_t off = (uint32_t)(r * 240 + c * 2);
    *(__nv_bfloat16*)(smem + O_SHI + off) = h;
    *(__nv_bfloat16*)(smem + O_SLO + off) = l;
  }
  __syncthreads();

  float acc[7][4];

  // Phase 1: quintic
  for (int it = 0; it < QI; it++) {
    gemm_ab(sb, O_SHI, O_SLO, O_SHI, O_SLO, wm, wn, lane, acc);
#pragma unroll
    for (int nt = 0; nt < 7; nt++) {
#pragma unroll
      for (int half = 0; half < 2; half++) {
        int row = wm * 16 + (lane >> 2) + half * 8;
        int col = wn * 56 + nt * 8 + 2 * (lane & 3);
        float a0 = acc[nt][half * 2 + 0], a1 = acc[nt][half * 2 + 1];
        __nv_bfloat16 h0 = __float2bfloat16(a0), h1 = __float2bfloat16(a1);
        float r0 = a0 - __bfloat162float(h0), r1 = a1 - __bfloat162float(h1);
        uint32_t hp = ((uint32_t)*(uint16_t*)&h1 << 16) | *(uint16_t*)&h0;
        uint32_t lp = pack_bf16(r0, r1);
        *(uint32_t*)(smem + O_YHI + row * 240 + col * 2) = hp;
        *(uint32_t*)(smem + O_YLO + row * 240 + col * 2) = lp;
      }
    }
    __syncthreads();
    gemm_ab(sb, O_YHI, O_YLO, O_YHI, O_YLO, wm, wn, lane, acc);
    __syncthreads();
#pragma unroll
    for (int nt = 0; nt < 7; nt++) {
#pragma unroll
      for (int half = 0; half < 2; half++) {
        int row = wm * 16 + (lane >> 2) + half * 8;
        int col = wn * 56 + nt * 8 + 2 * (lane & 3);
        float t01[2];
#pragma unroll
        for (int j = 0; j < 2; j++) {
          int c = col + j;
          uint32_t off = (uint32_t)(row * 240 + c * 2);
          float y = __bfloat162float(*(__nv_bfloat16*)(smem + O_YHI + off)) +
                    __bfloat162float(*(__nv_bfloat16*)(smem + O_YLO + off));
          t01[j] = ((row == c) ? QA : 0.f) + QB * y + QC * acc[nt][half * 2 + j];
        }
        __nv_bfloat16 h0 = __float2bfloat16(t01[0]), h1 = __float2bfloat16(t01[1]);
        float r0 = t01[0] - __bfloat162float(h0), r1 = t01[1] - __bfloat162float(h1);
        uint32_t hp = ((uint32_t)*(uint16_t*)&h1 << 16) | *(uint16_t*)&h0;
        uint32_t lp = pack_bf16(r0, r1);
        *(uint32_t*)(smem + O_THI + row * 240 + col * 2) = hp;
        *(uint32_t*)(smem + O_TLO + row * 240 + col * 2) = lp;
      }
    }
    __syncthreads();
    gemm_ab(sb, O_SHI, O_SLO, O_THI, O_TLO, wm, wn, lane, acc);
    __syncthreads();
#pragma unroll
    for (int nt = 0; nt < 7; nt++) {
#pragma unroll
      for (int half = 0; half < 2; half++) {
        int row = wm * 16 + (lane >> 2) + half * 8;
        int col = wn * 56 + nt * 8 + 2 * (lane & 3);
        int i0 = row * NSD + col;
        S32[i0]     = acc[nt][half * 2 + 0];
        S32[i0 + 1] = acc[nt][half * 2 + 1];
      }
    }
    __syncthreads();
    SYMMETRIZE_REFRESH();
    __syncthreads();
  }

  // Phase 2: cubic polish (symmetrize on odd iters only)
  for (int it = 0; it < CI; it++) {
    gemm_ab(sb, O_SHI, O_SLO, O_SHI, O_SLO, wm, wn, lane, acc);
#pragma unroll
    for (int nt = 0; nt < 7; nt++) {
#pragma unroll
      for (int half = 0; half < 2; half++) {
        int row = wm * 16 + (lane >> 2) + half * 8;
        int col = wn * 56 + nt * 8 + 2 * (lane & 3);
        float a0 = acc[nt][half * 2 + 0], a1 = acc[nt][half * 2 + 1];
        __nv_bfloat16 h0 = __float2bfloat16(a0), h1 = __float2bfloat16(a1);
        float r0 = a0 - __bfloat162float(h0), r1 = a1 - __bfloat162float(h1);
        uint32_t hp = ((uint32_t)*(uint16_t*)&h1 << 16) | *(uint16_t*)&h0;
        uint32_t lp = pack_bf16(r0, r1);
        *(uint32_t*)(smem + O_YHI + row * 240 + col * 2) = hp;
        *(uint32_t*)(smem + O_YLO + row * 240 + col * 2) = lp;
      }
    }
    __syncthreads();
    gemm_ab(sb, O_SHI, O_SLO, O_YHI, O_YLO, wm, wn, lane, acc);
    __syncthreads();
    if (it & 1) {
#pragma unroll
      for (int nt = 0; nt < 7; nt++) {
#pragma unroll
        for (int half = 0; half < 2; half++) {
          int row = wm * 16 + (lane >> 2) + half * 8;
          int col = wn * 56 + nt * 8 + 2 * (lane & 3);
          int i0 = row * NSD + col;
          S32[i0]     = 1.5f * S32[i0]     - 0.5f * acc[nt][half * 2 + 0];
          S32[i0 + 1] = 1.5f * S32[i0 + 1] - 0.5f * acc[nt][half * 2 + 1];
        }
      }
      __syncthreads();
      SYMMETRIZE_REFRESH();
    } else {
      // update + direct bf16 refresh (no symmetrize)
#pragma unroll
      for (int nt = 0; nt < 7; nt++) {
#pragma unroll
        for (int half = 0; half < 2; half++) {
          int row = wm * 16 + (lane >> 2) + half * 8;
          int col = wn * 56 + nt * 8 + 2 * (lane & 3);
          int i0 = row * NSD + col;
          float s0 = 1.5f * S32[i0]     - 0.5f * acc[nt][half * 2 + 0];
          float s1 = 1.5f * S32[i0 + 1] - 0.5f * acc[nt][half * 2 + 1];
          S32[i0] = s0;
          S32[i0 + 1] = s1;
          __nv_bfloat16 h0 = __float2bfloat16(s0), h1 = __float2bfloat16(s1);
          float r0 = s0 - __bfloat162float(h0), r1 = s1 - __bfloat162float(h1);
          uint32_t hp = ((uint32_t)*(uint16_t*)&h1 << 16) | *(uint16_t*)&h0;
          uint32_t lp = pack_bf16(r0, r1);
          *(uint32_t*)(smem + O_SHI + row * 240 + col * 2) = hp;
          *(uint32_t*)(smem + O_SLO + row * 240 + col * 2) = lp;
        }
      }
    }
    __syncthreads();
  }

  // final: W = S*Xn ; P = 0.5(X + f*W) + eps*I
  for (int idx = tid; idx < NSD * NSD; idx += NS_THREADS) {
    int r = idx / NSD, c = idx - (idx / NSD) * NSD;
    float v = 0.f;
    if (r < NA && c < NA)
      v = ((r == c) ? (1.0f - 1e-4f) : Rg[r * NA + c]) * invf;
    __nv_bfloat16 h = __float2bfloat16(v);
    __nv_bfloat16 l = __float2bfloat16(v - __bfloat162float(h));
    uint32_t off = (uint32_t)(r * 240 + c * 2);
    *(__nv_bfloat16*)(smem + O_YHI + off) = h;
    *(__nv_bfloat16*)(smem + O_YLO + off) = l;
  }
  __syncthreads();
  gemm_ab(sb, O_SHI, O_SLO, O_YHI, O_YLO, wm, wn, lane, acc);
  __syncthreads();
#pragma unroll
  for (int nt = 0; nt < 7; nt++) {
#pragma unroll
    for (int half = 0; half < 2; half++) {
      int row = wm * 16 + (lane >> 2) + half * 8;
      int col = wn * 56 + nt * 8 + 2 * (lane & 3);
#pragma unroll
      for (int j = 0; j < 2; j++) {
        int c = col + j;
        float Xg = 0.f;
        if (row < NA && c < NA)
          Xg = (row == c) ? (1.0f - 1e-4f) : Rg[row * NA + c];
        float P = 0.5f * (Xg + fnorm * acc[nt][half * 2 + j]) +
                  ((row == c) ? 1e-4f : 0.f);
        S32[row * NSD + c] = P;
      }
    }
  }
  __syncthreads();

  if (tid < NA) aux[16 + tid] = rsqrtf(fmaxf(S32[tid * (NSD + 1)], 1e-6f));
  __syncthreads();

  const float* vl = g_vols + b * NA;
  float* og = out + (size_t)b * NA * NA;
  for (int idx = tid; idx < NA * NA; idx += NS_THREADS) {
    int r = idx / NA, c = idx - (idx / NA) * NA;
    og[idx] = vl[r] * vl[c] * aux[16 + r] * aux[16 + c] * S32[r * NSD + c];
  }
}

// ---------------------------------------------------------------------------
extern "C" void kernel_launch(void* const* d_in, const int* in_sizes, int n_in,
                              void* d_out, int out_size) {
  const float* x   = (const float*)d_in[0];
  const float* vw1 = (const float*)d_in[1];
  const float* vb1 = (const float*)d_in[2];
  const float* vw2 = (const float*)d_in[3];
  const float* vb2 = (const float*)d_in[4];
  const float* cw1 = (const float*)d_in[5];
  const float* cb1 = (const float*)d_in[6];
  const float* cw2 = (const float*)d_in[7];
  const float* cb2 = (const float*)d_in[8];
  float* out = (float*)d_out;

  prep_w1t<<<HID, DM>>>(cw1);

  cudaFuncSetAttribute(pair_mma_kernel,
                       cudaFuncAttributeMaxDynamicSharedMemorySize, SMEM_PAIR);
  pair_mma_kernel<<<dim3(PTILES + VTILES, BATCH), 256, SMEM_PAIR>>>(
      x, vw1, vb1, vw2, vb2, cb1, cw2, cb2);

  cudaFuncSetAttribute(psd_kernel,
                       cudaFuncAttributeMaxDynamicSharedMemorySize, SMEM_NS);
  psd_kernel<<<BATCH, NS_THREADS, SMEM_NS>>>(out);
}